// round 2
// baseline (speedup 1.0000x reference)
#include <cuda_runtime.h>
#include <math.h>

// Problem constants
#define BB 32
#define HH 256
#define LL 2048
#define VV 50257
#define K2H 512

// d_out layout (outputs concatenated): log_probs[B*V], h_new[B*H], c_new[B*H], attn_weights[B*L]
#define OUT_H  (BB * VV)                 // 1608224
#define OUT_C  (OUT_H + BB * HH)         // 1616416
#define OUT_AW (OUT_C + BB * HH)         // 1624608

// ---------------- scratch (static device arrays; no allocation) ----------------
__device__ __align__(16) float g_w[HH];          // We^T v
__device__ __align__(16) float g_emb[BB * HH];
__device__ __align__(16) float g_scores[BB * LL];
__device__ __align__(16) float g_part[BB * 8 * HH];
__device__ __align__(16) float g_attnap[BB * HH];
__device__ __align__(16) float g_gates[4 * HH * BB];   // [g][b]
__device__ __align__(16) float g_x2[BB * K2H];         // concat(h_new, attn_applied) per b
__device__ float g_lse[BB];

static __device__ __forceinline__ unsigned long long ffma2(
    unsigned long long a, unsigned long long b, unsigned long long c) {
    unsigned long long d;
    asm("fma.rn.f32x2 %0, %1, %2, %3;" : "=l"(d) : "l"(a), "l"(b), "l"(c));
    return d;
}

static __device__ __forceinline__ float sigf(float x) { return 1.0f / (1.0f + expf(-x)); }

// ---------------- K1: w = We^T v ; embedding gather ----------------
__global__ void k_prep(const int* __restrict__ tokens,
                       const float* __restrict__ emb_table,
                       const float* __restrict__ W_attn,
                       const float* __restrict__ vvec) {
    int h = threadIdx.x;  // 0..255
    float acc = 0.0f;
    #pragma unroll 4
    for (int k = 0; k < HH; k++)
        acc = fmaf(vvec[k], W_attn[k * 512 + 256 + h], acc);
    g_w[h] = acc;
    for (int b = 0; b < BB; b++)
        g_emb[b * HH + h] = emb_table[(long long)tokens[b] * HH + h];
}

// ---------------- K2: scores[b,l] = enc[b,l,:] . w  (warp per 8 rows) ----------------
__global__ void k_scores(const float* __restrict__ enc) {
    int lane = threadIdx.x & 31;
    int gw = blockIdx.x * 8 + (threadIdx.x >> 5);
    int r0 = gw * 8;
    const float4* w4 = (const float4*)g_w;
    float4 wa = w4[lane];
    float4 wb = w4[32 + lane];
    float4 a[8], c[8];
    #pragma unroll
    for (int j = 0; j < 8; j++) {
        const float4* p = (const float4*)(enc + (size_t)(r0 + j) * HH);
        a[j] = p[lane];
        c[j] = p[32 + lane];
    }
    #pragma unroll
    for (int j = 0; j < 8; j++) {
        float s = a[j].x * wa.x + a[j].y * wa.y + a[j].z * wa.z + a[j].w * wa.w
                + c[j].x * wb.x + c[j].y * wb.y + c[j].z * wb.z + c[j].w * wb.w;
        #pragma unroll
        for (int off = 16; off > 0; off >>= 1)
            s += __shfl_xor_sync(0xffffffffu, s, off);
        if (lane == 0) g_scores[r0 + j] = s;
    }
}

// ---------------- K3: per-b softmax over L -> attn_weights in d_out ----------------
__global__ void k_softmax(float* __restrict__ out) {
    __shared__ float red[256];
    int b = blockIdx.x, t = threadIdx.x;
    float s[8];
    #pragma unroll
    for (int j = 0; j < 8; j++) s[j] = g_scores[b * LL + t + 256 * j];
    float m = s[0];
    #pragma unroll
    for (int j = 1; j < 8; j++) m = fmaxf(m, s[j]);
    red[t] = m; __syncthreads();
    for (int o = 128; o > 0; o >>= 1) { if (t < o) red[t] = fmaxf(red[t], red[t + o]); __syncthreads(); }
    m = red[0]; __syncthreads();
    float e[8], sum = 0.0f;
    #pragma unroll
    for (int j = 0; j < 8; j++) { e[j] = expf(s[j] - m); sum += e[j]; }
    red[t] = sum; __syncthreads();
    for (int o = 128; o > 0; o >>= 1) { if (t < o) red[t] += red[t + o]; __syncthreads(); }
    float inv = 1.0f / red[0];
    #pragma unroll
    for (int j = 0; j < 8; j++) out[OUT_AW + b * LL + t + 256 * j] = e[j] * inv;
}

// ---------------- K4: attn_applied partials over l-chunks ----------------
__global__ void k_attnpart(const float* __restrict__ enc, const float* __restrict__ out) {
    int c = blockIdx.x, b = blockIdx.y, h = threadIdx.x;
    int l0 = c * 256;
    float a0 = 0, a1 = 0, a2 = 0, a3 = 0;
    for (int l = 0; l < 256; l += 4) {
        int li = b * LL + l0 + l;
        float w0 = out[OUT_AW + li + 0];
        float w1 = out[OUT_AW + li + 1];
        float w2 = out[OUT_AW + li + 2];
        float w3 = out[OUT_AW + li + 3];
        a0 = fmaf(w0, enc[(size_t)(li + 0) * HH + h], a0);
        a1 = fmaf(w1, enc[(size_t)(li + 1) * HH + h], a1);
        a2 = fmaf(w2, enc[(size_t)(li + 2) * HH + h], a2);
        a3 = fmaf(w3, enc[(size_t)(li + 3) * HH + h], a3);
    }
    g_part[(b * 8 + c) * HH + h] = (a0 + a1) + (a2 + a3);
}

// ---------------- K5: reduce partials ----------------
__global__ void k_attnred() {
    int b = blockIdx.x, h = threadIdx.x;
    float s = 0.0f;
    #pragma unroll
    for (int c = 0; c < 8; c++) s += g_part[(b * 8 + c) * HH + h];
    g_attnap[b * HH + h] = s;
}

// ---------------- K6: LSTM gates GEMM (1024 gates x 32 b, K=768) ----------------
__global__ void k_gates(const float* __restrict__ W_ih, const float* __restrict__ b_ih,
                        const float* __restrict__ W_hh, const float* __restrict__ b_hh,
                        const float* __restrict__ hidden) {
    extern __shared__ float xT[];  // [768][32]
    int tid = threadIdx.x;
    for (int idx = tid; idx < 768 * 32; idx += 1024) {
        int k = idx >> 5, b = idx & 31;
        float v;
        if (k < 256)      v = g_emb[b * HH + k];
        else if (k < 512) v = g_attnap[b * HH + (k - 256)];
        else              v = hidden[b * HH + (k - 512)];
        xT[idx] = v;
    }
    __syncthreads();
    int g = blockIdx.x * 32 + (tid >> 5);
    int b = tid & 31;
    const float* wi = W_ih + g * 512;
    const float* wh = W_hh + g * 256;
    const float* xb = xT + b;
    float a0 = 0, a1 = 0, a2 = 0, a3 = 0;
    for (int k = 0; k < 512; k += 4) {
        a0 = fmaf(wi[k + 0], xb[32 * (k + 0)], a0);
        a1 = fmaf(wi[k + 1], xb[32 * (k + 1)], a1);
        a2 = fmaf(wi[k + 2], xb[32 * (k + 2)], a2);
        a3 = fmaf(wi[k + 3], xb[32 * (k + 3)], a3);
    }
    const float* hb = xT + 512 * 32 + b;
    for (int k = 0; k < 256; k += 4) {
        a0 = fmaf(wh[k + 0], hb[32 * (k + 0)], a0);
        a1 = fmaf(wh[k + 1], hb[32 * (k + 1)], a1);
        a2 = fmaf(wh[k + 2], hb[32 * (k + 2)], a2);
        a3 = fmaf(wh[k + 3], hb[32 * (k + 3)], a3);
    }
    g_gates[g * 32 + b] = ((a0 + a1) + (a2 + a3)) + b_ih[g] + b_hh[g];
}

// ---------------- K7: LSTM pointwise; fill x2 ----------------
__global__ void k_lstm(const float* __restrict__ cell, float* __restrict__ out) {
    int b = blockIdx.x, h = threadIdx.x;
    float ig = g_gates[(0 * HH + h) * 32 + b];
    float fg = g_gates[(1 * HH + h) * 32 + b];
    float gg = g_gates[(2 * HH + h) * 32 + b];
    float og = g_gates[(3 * HH + h) * 32 + b];
    float c_new = sigf(fg) * cell[b * HH + h] + sigf(ig) * tanhf(gg);
    float h_new = sigf(og) * tanhf(c_new);
    out[OUT_H + b * HH + h] = h_new;
    out[OUT_C + b * HH + h] = c_new;
    g_x2[b * K2H + h] = h_new;
    g_x2[b * K2H + 256 + h] = g_attnap[b * HH + h];
}

// ---------------- K8: logits GEMM (V x 32, K=512) with packed f32x2 FMA ----------------
__global__ void k_logits(const float* __restrict__ Wo, const float* __restrict__ bo,
                         float* __restrict__ out) {
    __shared__ __align__(16) float Wt[32 * 130];   // k-major transposed W tile [k][row], stride 130
    __shared__ __align__(16) float xs2[32 * 64];   // duplicated x: [k][2b], pairs (x,x)
    int tid = threadIdx.x;
    int v0 = blockIdx.x * 128;
    unsigned long long acc[2][4];
    #pragma unroll
    for (int p = 0; p < 2; p++)
        #pragma unroll
        for (int j = 0; j < 4; j++) acc[p][j] = 0ull;
    int bq = tid & 7, vq = tid >> 3;

    for (int kt = 0; kt < 512; kt += 32) {
        // stage W tile (coalesced 128B per 8 lanes), transpose into k-major smem
        #pragma unroll
        for (int jj = 0; jj < 4; jj++) {
            int idx = tid + 256 * jj;
            int row = idx >> 3, q = idx & 7;
            int vr = v0 + row;
            float4 w = make_float4(0.f, 0.f, 0.f, 0.f);
            if (vr < VV) w = *(const float4*)(Wo + (size_t)vr * 512 + kt + 4 * q);
            int kk = 4 * q;
            Wt[(kk + 0) * 130 + row] = w.x;
            Wt[(kk + 1) * 130 + row] = w.y;
            Wt[(kk + 2) * 130 + row] = w.z;
            Wt[(kk + 3) * 130 + row] = w.w;
        }
        // stage x tile, duplicated for f32x2
        {
            int b = tid & 31, k4 = tid >> 5;
            float4 x = *(const float4*)(g_x2 + b * K2H + kt + 4 * k4);
            float xv[4] = {x.x, x.y, x.z, x.w};
            #pragma unroll
            for (int j = 0; j < 4; j++) {
                int kk = 4 * k4 + j;
                xs2[kk * 64 + 2 * b + 0] = xv[j];
                xs2[kk * 64 + 2 * b + 1] = xv[j];
            }
        }
        __syncthreads();
        #pragma unroll
        for (int k = 0; k < 32; k++) {
            const float* wr = Wt + k * 130 + 4 * vq;
            unsigned long long w01 = *(const unsigned long long*)(wr);
            unsigned long long w23 = *(const unsigned long long*)(wr + 2);
            const unsigned long long* xr = (const unsigned long long*)(xs2 + k * 64 + 8 * bq);
            #pragma unroll
            for (int j = 0; j < 4; j++) {
                unsigned long long xj = xr[j];
                acc[0][j] = ffma2(w01, xj, acc[0][j]);
                acc[1][j] = ffma2(w23, xj, acc[1][j]);
            }
        }
        __syncthreads();
    }
    #pragma unroll
    for (int p = 0; p < 2; p++)
        #pragma unroll
        for (int j = 0; j < 4; j++) {
            int vv = v0 + 4 * vq + 2 * p;
            int bb = 4 * bq + j;
            float lo = __uint_as_float((unsigned)(acc[p][j] & 0xffffffffull));
            float hi = __uint_as_float((unsigned)(acc[p][j] >> 32));
            if (vv < VV)     out[(size_t)bb * VV + vv] = lo + bo[vv];
            if (vv + 1 < VV) out[(size_t)bb * VV + vv + 1] = hi + bo[vv + 1];
        }
}

// ---------------- K9: per-b logsumexp over V ----------------
__global__ void k_lse(const float* __restrict__ out) {
    __shared__ float red[1024];
    int b = blockIdx.x, t = threadIdx.x;
    const float* p = out + (size_t)b * VV;
    float m = -1e30f;
    for (int i = t; i < VV; i += 1024) m = fmaxf(m, p[i]);
    red[t] = m; __syncthreads();
    for (int o = 512; o > 0; o >>= 1) { if (t < o) red[t] = fmaxf(red[t], red[t + o]); __syncthreads(); }
    m = red[0]; __syncthreads();
    float s = 0.0f;
    for (int i = t; i < VV; i += 1024) s += expf(p[i] - m);
    red[t] = s; __syncthreads();
    for (int o = 512; o > 0; o >>= 1) { if (t < o) red[t] += red[t + o]; __syncthreads(); }
    if (t == 0) g_lse[b] = m + logf(red[0]);
}

// ---------------- K10: log_probs = logits - lse ----------------
__global__ void k_sub(float* __restrict__ out) {
    int b = blockIdx.y;
    int v = blockIdx.x * 256 + threadIdx.x;
    if (v < VV) out[(size_t)b * VV + v] -= g_lse[b];
}

extern "C" void kernel_launch(void* const* d_in, const int* in_sizes, int n_in,
                              void* d_out, int out_size) {
    const int*   tokens    = (const int*)d_in[0];
    const float* hidden    = (const float*)d_in[1];
    const float* cell      = (const float*)d_in[2];
    const float* enc       = (const float*)d_in[3];
    const float* emb_table = (const float*)d_in[4];
    const float* W_attn    = (const float*)d_in[5];
    // d_in[6] = b_attn (unused: softmax shift-invariance), d_in[7] = v
    const float* vvec      = (const float*)d_in[7];
    const float* W_ih      = (const float*)d_in[8];
    const float* b_ih      = (const float*)d_in[9];
    const float* W_hh      = (const float*)d_in[10];
    const float* b_hh      = (const float*)d_in[11];
    const float* W_out     = (const float*)d_in[12];
    const float* b_out     = (const float*)d_in[13];
    float* out = (float*)d_out;

    cudaFuncSetAttribute(k_gates, cudaFuncAttributeMaxDynamicSharedMemorySize, 98304);

    k_prep<<<1, 256>>>(tokens, emb_table, W_attn, vvec);
    k_scores<<<1024, 256>>>(enc);
    k_softmax<<<BB, 256>>>(out);
    {
        dim3 g(8, BB);
        k_attnpart<<<g, 256>>>(enc, out);
    }
    k_attnred<<<BB, 256>>>();
    k_gates<<<32, 1024, 98304>>>(W_ih, b_ih, W_hh, b_hh, hidden);
    k_lstm<<<BB, 256>>>(cell, out);
    k_logits<<<(VV + 127) / 128, 256>>>(W_out, b_out, out);
    k_lse<<<BB, 1024>>>(out);
    {
        dim3 g((VV + 255) / 256, BB);
        k_sub<<<g, 256>>>(out);
    }
}

// round 7
// speedup vs baseline: 1.0081x; 1.0081x over previous
#include <cuda_runtime.h>
#include <math.h>

#define BB 32
#define HH 256
#define LL 2048
#define VV 50257
#define K2H 512

// d_out layout: log_probs[B*V], h_new[B*H], c_new[B*H], attn_weights[B*L]
#define OUT_H  (BB * VV)
#define OUT_C  (OUT_H + BB * HH)
#define OUT_AW (OUT_C + BB * HH)

// ---------------- scratch ----------------
__device__ __align__(16) float g_w[HH];              // We^T v
__device__ __align__(16) float g_scores[BB * LL];
__device__ __align__(16) float g_part[BB * 32 * HH]; // attn partials per l-chunk
__device__ __align__(16) float g_xT[768 * 32];       // [k][b] transposed LSTM input
__device__ __align__(16) float g_gpart[2 * 1024 * 32]; // gate partials [ks][g][b]
__device__ __align__(16) float g_x2[BB * K2H];       // concat(h_new, attnap) per b
__device__ float g_lse[BB];

static __device__ __forceinline__ unsigned long long ffma2(
    unsigned long long a, unsigned long long b, unsigned long long c) {
    unsigned long long d;
    asm("fma.rn.f32x2 %0, %1, %2, %3;" : "=l"(d) : "l"(a), "l"(b), "l"(c));
    return d;
}

static __device__ __forceinline__ float sigf(float x) { return 1.0f / (1.0f + expf(-x)); }

// ---------------- K0: w = We^T v (k-split over 4 groups, 1024 threads) ----------------
__global__ void k_w(const float* __restrict__ W_attn, const float* __restrict__ vvec) {
    __shared__ float part[1024];
    int t = threadIdx.x;
    int h = t & 255, kq = t >> 8;
    int kb = kq * 64;
    float a0 = 0, a1 = 0, a2 = 0, a3 = 0;
    #pragma unroll 4
    for (int i = 0; i < 64; i += 4) {
        a0 = fmaf(vvec[kb + i + 0], W_attn[(kb + i + 0) * 512 + 256 + h], a0);
        a1 = fmaf(vvec[kb + i + 1], W_attn[(kb + i + 1) * 512 + 256 + h], a1);
        a2 = fmaf(vvec[kb + i + 2], W_attn[(kb + i + 2) * 512 + 256 + h], a2);
        a3 = fmaf(vvec[kb + i + 3], W_attn[(kb + i + 3) * 512 + 256 + h], a3);
    }
    part[t] = (a0 + a1) + (a2 + a3);
    __syncthreads();
    if (t < 256) g_w[t] = part[t] + part[256 + t] + part[512 + t] + part[768 + t];
}

// ---------------- K0b: embedding gather + hidden -> g_xT ----------------
__global__ void k_emb(const int* __restrict__ tokens,
                      const float* __restrict__ emb_table,
                      const float* __restrict__ hidden) {
    int b = blockIdx.x, h = threadIdx.x;
    int tok = tokens[b];
    g_xT[h * 32 + b] = emb_table[(long long)tok * HH + h];
    g_xT[(512 + h) * 32 + b] = hidden[b * HH + h];
}

// ---------------- K1: scores[b,l] = enc[b,l,:] . w ----------------
__global__ void k_scores(const float* __restrict__ enc) {
    int lane = threadIdx.x & 31;
    int gw = blockIdx.x * 8 + (threadIdx.x >> 5);
    int r0 = gw * 8;
    const float4* w4 = (const float4*)g_w;
    float4 wa = w4[lane];
    float4 wb = w4[32 + lane];
    float4 a[8], c[8];
    #pragma unroll
    for (int j = 0; j < 8; j++) {
        const float4* p = (const float4*)(enc + (size_t)(r0 + j) * HH);
        a[j] = p[lane];
        c[j] = p[32 + lane];
    }
    #pragma unroll
    for (int j = 0; j < 8; j++) {
        float s = a[j].x * wa.x + a[j].y * wa.y + a[j].z * wa.z + a[j].w * wa.w
                + c[j].x * wb.x + c[j].y * wb.y + c[j].z * wb.z + c[j].w * wb.w;
        #pragma unroll
        for (int off = 16; off > 0; off >>= 1)
            s += __shfl_xor_sync(0xffffffffu, s, off);
        if (lane == 0) g_scores[r0 + j] = s;
    }
}

// ---------------- K2: per-b softmax -> attn_weights in d_out ----------------
__global__ void k_softmax(float* __restrict__ out) {
    __shared__ float red[256];
    int b = blockIdx.x, t = threadIdx.x;
    float s[8];
    #pragma unroll
    for (int j = 0; j < 8; j++) s[j] = g_scores[b * LL + t + 256 * j];
    float m = s[0];
    #pragma unroll
    for (int j = 1; j < 8; j++) m = fmaxf(m, s[j]);
    red[t] = m; __syncthreads();
    for (int o = 128; o > 0; o >>= 1) { if (t < o) red[t] = fmaxf(red[t], red[t + o]); __syncthreads(); }
    m = red[0]; __syncthreads();
    float e[8], sum = 0.0f;
    #pragma unroll
    for (int j = 0; j < 8; j++) { e[j] = expf(s[j] - m); sum += e[j]; }
    red[t] = sum; __syncthreads();
    for (int o = 128; o > 0; o >>= 1) { if (t < o) red[t] += red[t + o]; __syncthreads(); }
    float inv = 1.0f / red[0];
    #pragma unroll
    for (int j = 0; j < 8; j++) out[OUT_AW + b * LL + t + 256 * j] = e[j] * inv;
}

// ---------------- K3: attn_applied partials (32 l-chunks x 32 b, float4 over H) ----------------
__global__ void k_attnpart(const float* __restrict__ enc, const float* __restrict__ out) {
    int c = blockIdx.x, b = blockIdx.y;
    int t = threadIdx.x;
    int hq = t & 63, lg = t >> 6;
    int base = b * LL + c * 64 + lg;
    const float4* e4 = (const float4*)enc;
    float4 a0 = make_float4(0,0,0,0), a1 = a0, a2 = a0, a3 = a0;
    #pragma unroll
    for (int j = 0; j < 64; j += 16) {
        int l0 = base + j;
        float w0 = out[OUT_AW + l0 + 0];
        float w1 = out[OUT_AW + l0 + 4];
        float w2 = out[OUT_AW + l0 + 8];
        float w3 = out[OUT_AW + l0 + 12];
        float4 e0 = e4[(size_t)(l0 + 0)  * 64 + hq];
        float4 e1 = e4[(size_t)(l0 + 4)  * 64 + hq];
        float4 e2 = e4[(size_t)(l0 + 8)  * 64 + hq];
        float4 e3 = e4[(size_t)(l0 + 12) * 64 + hq];
        a0.x = fmaf(w0, e0.x, a0.x); a0.y = fmaf(w0, e0.y, a0.y);
        a0.z = fmaf(w0, e0.z, a0.z); a0.w = fmaf(w0, e0.w, a0.w);
        a1.x = fmaf(w1, e1.x, a1.x); a1.y = fmaf(w1, e1.y, a1.y);
        a1.z = fmaf(w1, e1.z, a1.z); a1.w = fmaf(w1, e1.w, a1.w);
        a2.x = fmaf(w2, e2.x, a2.x); a2.y = fmaf(w2, e2.y, a2.y);
        a2.z = fmaf(w2, e2.z, a2.z); a2.w = fmaf(w2, e2.w, a2.w);
        a3.x = fmaf(w3, e3.x, a3.x); a3.y = fmaf(w3, e3.y, a3.y);
        a3.z = fmaf(w3, e3.z, a3.z); a3.w = fmaf(w3, e3.w, a3.w);
    }
    __shared__ float4 sm[4][64];
    float4 s;
    s.x = (a0.x + a1.x) + (a2.x + a3.x);
    s.y = (a0.y + a1.y) + (a2.y + a3.y);
    s.z = (a0.z + a1.z) + (a2.z + a3.z);
    s.w = (a0.w + a1.w) + (a2.w + a3.w);
    sm[lg][hq] = s;
    __syncthreads();
    if (t < 64) {
        float4 r0 = sm[0][t], r1 = sm[1][t], r2 = sm[2][t], r3 = sm[3][t];
        float4 r;
        r.x = (r0.x + r1.x) + (r2.x + r3.x);
        r.y = (r0.y + r1.y) + (r2.y + r3.y);
        r.z = (r0.z + r1.z) + (r2.z + r3.z);
        r.w = (r0.w + r1.w) + (r2.w + r3.w);
        *(float4*)(g_part + (size_t)(b * 32 + c) * 256 + 4 * t) = r;
    }
}

// ---------------- K4: reduce attn partials -> g_x2 / g_xT ----------------
__global__ void k_attnred() {
    int b = blockIdx.x, h = threadIdx.x;
    float s = 0.0f;
    #pragma unroll
    for (int c = 0; c < 32; c++) s += g_part[(size_t)(b * 32 + c) * 256 + h];
    g_x2[b * K2H + 256 + h] = s;
    g_xT[(256 + h) * 32 + b] = s;
}

// ---------------- K5: LSTM gates GEMM, 4 g-rows/warp, 2-way K-split ----------------
__global__ void k_gates(const float* __restrict__ W_ih, const float* __restrict__ b_ih,
                        const float* __restrict__ W_hh, const float* __restrict__ b_hh) {
    int t = threadIdx.x;
    int lane = t & 31, w = t >> 5;
    int g0 = blockIdx.x * 32 + w * 4;
    int ks = blockIdx.y;
    float acc0 = 0, acc1 = 0, acc2 = 0, acc3 = 0;

    auto span = [&](int k_lo, int k_hi, const float* W, int rstride, int koff) {
        for (int k = k_lo; k < k_hi; k += 4) {
            float x0 = g_xT[(k + 0) * 32 + lane];
            float x1 = g_xT[(k + 1) * 32 + lane];
            float x2 = g_xT[(k + 2) * 32 + lane];
            float x3 = g_xT[(k + 3) * 32 + lane];
            float4 w0 = *(const float4*)(W + (size_t)(g0 + 0) * rstride + (k - koff));
            float4 w1 = *(const float4*)(W + (size_t)(g0 + 1) * rstride + (k - koff));
            float4 w2 = *(const float4*)(W + (size_t)(g0 + 2) * rstride + (k - koff));
            float4 w3 = *(const float4*)(W + (size_t)(g0 + 3) * rstride + (k - koff));
            acc0 = fmaf(w0.x, x0, fmaf(w0.y, x1, fmaf(w0.z, x2, fmaf(w0.w, x3, acc0))));
            acc1 = fmaf(w1.x, x0, fmaf(w1.y, x1, fmaf(w1.z, x2, fmaf(w1.w, x3, acc1))));
            acc2 = fmaf(w2.x, x0, fmaf(w2.y, x1, fmaf(w2.z, x2, fmaf(w2.w, x3, acc2))));
            acc3 = fmaf(w3.x, x0, fmaf(w3.y, x1, fmaf(w3.z, x2, fmaf(w3.w, x3, acc3))));
        }
    };
    if (ks == 0) {
        span(0, 384, W_ih, 512, 0);
        acc0 += b_ih[g0 + 0] + b_hh[g0 + 0];
        acc1 += b_ih[g0 + 1] + b_hh[g0 + 1];
        acc2 += b_ih[g0 + 2] + b_hh[g0 + 2];
        acc3 += b_ih[g0 + 3] + b_hh[g0 + 3];
    } else {
        span(384, 512, W_ih, 512, 0);
        span(512, 768, W_hh, 256, 512);
    }
    float* gp = g_gpart + ks * 32768;
    gp[(g0 + 0) * 32 + lane] = acc0;
    gp[(g0 + 1) * 32 + lane] = acc1;
    gp[(g0 + 2) * 32 + lane] = acc2;
    gp[(g0 + 3) * 32 + lane] = acc3;
}

// ---------------- K6: LSTM pointwise ----------------
__global__ void k_lstm(const float* __restrict__ cell, float* __restrict__ out) {
    int b = blockIdx.x, h = threadIdx.x;
    float ig = g_gpart[(0 * HH + h) * 32 + b] + g_gpart[32768 + (0 * HH + h) * 32 + b];
    float fg = g_gpart[(1 * HH + h) * 32 + b] + g_gpart[32768 + (1 * HH + h) * 32 + b];
    float gg = g_gpart[(2 * HH + h) * 32 + b] + g_gpart[32768 + (2 * HH + h) * 32 + b];
    float og = g_gpart[(3 * HH + h) * 32 + b] + g_gpart[32768 + (3 * HH + h) * 32 + b];
    float c_new = sigf(fg) * cell[b * HH + h] + sigf(ig) * tanhf(gg);
    float h_new = sigf(og) * tanhf(c_new);
    out[OUT_H + b * HH + h] = h_new;
    out[OUT_C + b * HH + h] = c_new;
    g_x2[b * K2H + h] = h_new;
}

// ---------------- K7: logits GEMM (V x 32, K=512), f32x2 FMA, double-buffered ----------------
__global__ void __launch_bounds__(256) k_logits(const float* __restrict__ Wo,
                                                const float* __restrict__ bo,
                                                float* __restrict__ out) {
    extern __shared__ float smem[];
    float* Wt[2] = { smem, smem + 4160 };          // [k][row], stride 130
    float* Xs[2] = { smem + 8320, smem + 8320 + 2048 };  // [k][2b] duplicated pairs

    int tid = threadIdx.x;
    int v0 = blockIdx.x * 128;
    int bq = tid & 7, vq = tid >> 3;
    int srow = tid >> 3;          // staging rows 0..31 per jj
    int sq = tid & 7;
    int xb = tid & 31, xk4 = tid >> 5;

    float4 wreg[4];
    float4 xreg;

    auto load_tile = [&](int kt) {
        #pragma unroll
        for (int jj = 0; jj < 4; jj++) {
            int row = srow + 32 * jj;
            int vr = v0 + row;
            wreg[jj] = (vr < VV) ? *(const float4*)(Wo + (size_t)vr * 512 + kt + 4 * sq)
                                 : make_float4(0.f, 0.f, 0.f, 0.f);
        }
        xreg = *(const float4*)(g_x2 + xb * K2H + kt + 4 * xk4);
    };
    auto store_tile = [&](int s) {
        #pragma unroll
        for (int jj = 0; jj < 4; jj++) {
            int row = srow + 32 * jj;
            int kk = 4 * sq;
            Wt[s][(kk + 0) * 130 + row] = wreg[jj].x;
            Wt[s][(kk + 1) * 130 + row] = wreg[jj].y;
            Wt[s][(kk + 2) * 130 + row] = wreg[jj].z;
            Wt[s][(kk + 3) * 130 + row] = wreg[jj].w;
        }
        float xv[4] = { xreg.x, xreg.y, xreg.z, xreg.w };
        #pragma unroll
        for (int j = 0; j < 4; j++) {
            int kk = 4 * xk4 + j;
            Xs[s][kk * 64 + 2 * xb + 0] = xv[j];
            Xs[s][kk * 64 + 2 * xb + 1] = xv[j];
        }
    };

    unsigned long long acc[2][4];
    #pragma unroll
    for (int p = 0; p < 2; p++)
        #pragma unroll
        for (int j = 0; j < 4; j++) acc[p][j] = 0ull;

    load_tile(0);
    store_tile(0);
    __syncthreads();

    for (int it = 0; it < 16; it++) {
        int cur = it & 1, nxt = cur ^ 1;
        if (it < 15) load_tile((it + 1) * 32);
        const float* W = Wt[cur];
        const float* X = Xs[cur];
        #pragma unroll
        for (int k = 0; k < 32; k++) {
            const float* wr = W + k * 130 + 4 * vq;
            unsigned long long w01 = *(const unsigned long long*)(wr);
            unsigned long long w23 = *(const unsigned long long*)(wr + 2);
            const unsigned long long* xr = (const unsigned long long*)(X + k * 64 + 8 * bq);
            #pragma unroll
            for (int j = 0; j < 4; j++) {
                unsigned long long xj = xr[j];
                acc[0][j] = ffma2(w01, xj, acc[0][j]);
                acc[1][j] = ffma2(w23, xj, acc[1][j]);
            }
        }
        if (it < 15) store_tile(nxt);
        __syncthreads();
    }

    #pragma unroll
    for (int p = 0; p < 2; p++)
        #pragma unroll
        for (int j = 0; j < 4; j++) {
            int vv = v0 + 4 * vq + 2 * p;
            int bb = 4 * bq + j;
            float lo = __uint_as_float((unsigned)(acc[p][j] & 0xffffffffull));
            float hi = __uint_as_float((unsigned)(acc[p][j] >> 32));
            if (vv < VV)     out[(size_t)bb * VV + vv] = lo + bo[vv];
            if (vv + 1 < VV) out[(size_t)bb * VV + vv + 1] = hi + bo[vv + 1];
        }
}

// ---------------- K8: per-b logsumexp over V ----------------
__global__ void k_lse(const float* __restrict__ out) {
    __shared__ float red[1024];
    int b = blockIdx.x, t = threadIdx.x;
    const float* p = out + (size_t)b * VV;
    float m = -1e30f;
    for (int i = t; i < VV; i += 1024) m = fmaxf(m, p[i]);
    red[t] = m; __syncthreads();
    for (int o = 512; o > 0; o >>= 1) { if (t < o) red[t] = fmaxf(red[t], red[t + o]); __syncthreads(); }
    m = red[0]; __syncthreads();
    float s = 0.0f;
    for (int i = t; i < VV; i += 1024) s += expf(p[i] - m);
    red[t] = s; __syncthreads();
    for (int o = 512; o > 0; o >>= 1) { if (t < o) red[t] += red[t + o]; __syncthreads(); }
    if (t == 0) g_lse[b] = m + logf(red[0]);
}

// ---------------- K9: log_probs = logits - lse ----------------
__global__ void k_sub(float* __restrict__ out) {
    int b = blockIdx.y;
    int v = blockIdx.x * 256 + threadIdx.x;
    if (v < VV) out[(size_t)b * VV + v] -= g_lse[b];
}

extern "C" void kernel_launch(void* const* d_in, const int* in_sizes, int n_in,
                              void* d_out, int out_size) {
    const int*   tokens    = (const int*)d_in[0];
    const float* hidden    = (const float*)d_in[1];
    const float* cell      = (const float*)d_in[2];
    const float* enc       = (const float*)d_in[3];
    const float* emb_table = (const float*)d_in[4];
    const float* W_attn    = (const float*)d_in[5];
    // d_in[6] = b_attn unused (softmax shift-invariance)
    const float* vvec      = (const float*)d_in[7];
    const float* W_ih      = (const float*)d_in[8];
    const float* b_ih      = (const float*)d_in[9];
    const float* W_hh      = (const float*)d_in[10];
    const float* b_hh      = (const float*)d_in[11];
    const float* W_out     = (const float*)d_in[12];
    const float* b_out     = (const float*)d_in[13];
    float* out = (float*)d_out;

    // Idempotent, not a stream op (not captured); no static guard per harness rules.
    cudaFuncSetAttribute(k_logits, cudaFuncAttributeMaxDynamicSharedMemorySize, 50176);

    k_w<<<1, 1024>>>(W_attn, vvec);
    k_emb<<<BB, 256>>>(tokens, emb_table, hidden);
    k_scores<<<1024, 256>>>(enc);
    k_softmax<<<BB, 256>>>(out);
    {
        dim3 g(32, BB);
        k_attnpart<<<g, 256>>>(enc, out);
    }
    k_attnred<<<BB, 256>>>();
    {
        dim3 g(32, 2);
        k_gates<<<g, 256>>>(W_ih, b_ih, W_hh, b_hh);
    }
    k_lstm<<<BB, 256>>>(cell, out);
    k_logits<<<(VV + 127) / 128, 256, 50176>>>(W_out, b_out, out);
    k_lse<<<BB, 1024>>>(out);
    {
        dim3 g((VV + 255) / 256, BB);
        k_sub<<<g, 256>>>(out);
    }
}

// round 8
// speedup vs baseline: 1.6155x; 1.6025x over previous
#include <cuda_runtime.h>
#include <math.h>

#define BB 32
#define HH 256
#define LL 2048
#define VV 50257
#define K2H 512

// d_out layout: log_probs[B*V], h_new[B*H], c_new[B*H], attn_weights[B*L]
#define OUT_H  (BB * VV)
#define OUT_C  (OUT_H + BB * HH)
#define OUT_AW (OUT_C + BB * HH)

// ---------------- scratch ----------------
__device__ __align__(16) float g_wpart[4 * 256];       // partial We^T v
__device__ __align__(16) float g_scores[BB * LL];
__device__ __align__(16) float g_ms[BB * 32];          // per-chunk max
__device__ __align__(16) float g_Ss[BB * 32];          // per-chunk expsum
__device__ __align__(16) float g_part[BB * 32 * HH];   // per-chunk weighted partials
__device__ __align__(16) float g_xT[768 * 32];         // [k][b] LSTM input transposed
__device__ __align__(16) float g_gpart[2 * 1024 * 32]; // gate partials [ks][g][b]
__device__ __align__(16) float g_x2[BB * K2H];         // concat(h_new, attnap) per b
__device__ float g_lse[BB];

static __device__ __forceinline__ unsigned long long ffma2(
    unsigned long long a, unsigned long long b, unsigned long long c) {
    unsigned long long d;
    asm("fma.rn.f32x2 %0, %1, %2, %3;" : "=l"(d) : "l"(a), "l"(b), "l"(c));
    return d;
}

static __device__ __forceinline__ float sigf(float x) { return 1.0f / (1.0f + expf(-x)); }

// ---------------- K1: init — w partials (blocks 0-3), emb+hidden transpose (blocks 4-35) ----
__global__ void k_init(const int* __restrict__ tokens,
                       const float* __restrict__ emb_table,
                       const float* __restrict__ hidden,
                       const float* __restrict__ W_attn,
                       const float* __restrict__ vvec) {
    int t = threadIdx.x;
    if (blockIdx.x < 4) {
        int kb = blockIdx.x * 64;
        float a0 = 0, a1 = 0, a2 = 0, a3 = 0;
        #pragma unroll 4
        for (int i = 0; i < 64; i += 4) {
            a0 = fmaf(vvec[kb + i + 0], W_attn[(kb + i + 0) * 512 + 256 + t], a0);
            a1 = fmaf(vvec[kb + i + 1], W_attn[(kb + i + 1) * 512 + 256 + t], a1);
            a2 = fmaf(vvec[kb + i + 2], W_attn[(kb + i + 2) * 512 + 256 + t], a2);
            a3 = fmaf(vvec[kb + i + 3], W_attn[(kb + i + 3) * 512 + 256 + t], a3);
        }
        g_wpart[blockIdx.x * 256 + t] = (a0 + a1) + (a2 + a3);
    } else {
        int b = blockIdx.x - 4;
        int tok = tokens[b];
        g_xT[t * 32 + b] = emb_table[(long long)tok * HH + t];
        g_xT[(512 + t) * 32 + b] = hidden[b * HH + t];
    }
}

// ---------------- K2: fused attention pass 1 — per (chunk c, batch b) ----------------
// Loads 64x256 enc chunk once into smem; computes scores, chunk softmax stats,
// and weighted partial sums. Single pass over enc (64 MB total).
__global__ void kA(const float* __restrict__ enc) {
    extern __shared__ float es[];       // 64*256 floats = 64 KB
    __shared__ float w_s[256];
    __shared__ float score_s[64];
    __shared__ float esc_s[64];
    __shared__ float mred_s[1];
    int c = blockIdx.x, b = blockIdx.y;
    int t = threadIdx.x;
    int lane = t & 31, wid = t >> 5;

    // reconstruct w = We^T v from partials (4 KB, L2-hot)
    w_s[t] = g_wpart[t] + g_wpart[256 + t] + g_wpart[512 + t] + g_wpart[768 + t];

    // stage enc chunk (16 float4 per thread, coalesced)
    const float4* e4 = (const float4*)(enc + ((size_t)b * LL + c * 64) * HH);
    float4* s4 = (float4*)es;
    #pragma unroll
    for (int i = 0; i < 16; i++) s4[t + 256 * i] = e4[t + 256 * i];
    __syncthreads();

    // scores: warp per row
    const float4* w4 = (const float4*)w_s;
    float4 wa = w4[lane], wb = w4[32 + lane];
    #pragma unroll
    for (int r = wid; r < 64; r += 8) {
        const float4* row = (const float4*)(es + r * 256);
        float4 a = row[lane], cc = row[32 + lane];
        float s = a.x * wa.x + a.y * wa.y + a.z * wa.z + a.w * wa.w
                + cc.x * wb.x + cc.y * wb.y + cc.z * wb.z + cc.w * wb.w;
        #pragma unroll
        for (int off = 16; off > 0; off >>= 1)
            s += __shfl_xor_sync(0xffffffffu, s, off);
        if (lane == 0) {
            score_s[r] = s;
            g_scores[b * LL + c * 64 + r] = s;
        }
    }
    __syncthreads();

    // chunk max
    if (t < 32) {
        float m = fmaxf(score_s[t], score_s[t + 32]);
        #pragma unroll
        for (int off = 16; off > 0; off >>= 1)
            m = fmaxf(m, __shfl_xor_sync(0xffffffffu, m, off));
        if (lane == 0) mred_s[0] = m;
    }
    __syncthreads();
    float m_c = mred_s[0];
    if (t < 64) esc_s[t] = expf(score_s[t] - m_c);
    __syncthreads();
    if (t < 32) {
        float sum = esc_s[t] + esc_s[t + 32];
        #pragma unroll
        for (int off = 16; off > 0; off >>= 1)
            sum += __shfl_xor_sync(0xffffffffu, sum, off);
        if (lane == 0) { g_ms[b * 32 + c] = m_c; g_Ss[b * 32 + c] = sum; }
    }

    // weighted partial sums: thread = h
    float a0 = 0, a1 = 0, a2 = 0, a3 = 0;
    #pragma unroll
    for (int l = 0; l < 64; l += 4) {
        a0 = fmaf(esc_s[l + 0], es[(l + 0) * 256 + t], a0);
        a1 = fmaf(esc_s[l + 1], es[(l + 1) * 256 + t], a1);
        a2 = fmaf(esc_s[l + 2], es[(l + 2) * 256 + t], a2);
        a3 = fmaf(esc_s[l + 3], es[(l + 3) * 256 + t], a3);
    }
    g_part[((size_t)b * 32 + c) * 256 + t] = (a0 + a1) + (a2 + a3);
}

// ---------------- K3: attention combine — global stats, weights, attn_applied ----------------
__global__ void kB(float* __restrict__ out) {
    __shared__ float scale_s[32];
    __shared__ float stat_s[2];
    int b = blockIdx.x, t = threadIdx.x;
    if (t < 32) {
        float mc = g_ms[b * 32 + t];
        float m = mc;
        #pragma unroll
        for (int off = 16; off > 0; off >>= 1)
            m = fmaxf(m, __shfl_xor_sync(0xffffffffu, m, off));
        float e = expf(mc - m);
        float z = g_Ss[b * 32 + t] * e;
        #pragma unroll
        for (int off = 16; off > 0; off >>= 1)
            z += __shfl_xor_sync(0xffffffffu, z, off);
        scale_s[t] = e / z;
        if (t == 0) { stat_s[0] = m; stat_s[1] = 1.0f / z; }
    }
    __syncthreads();
    // attn_applied for h = t (4-way MLP)
    float s0 = 0, s1 = 0, s2 = 0, s3 = 0;
    #pragma unroll
    for (int c = 0; c < 32; c += 4) {
        s0 = fmaf(g_part[((size_t)b * 32 + c + 0) * 256 + t], scale_s[c + 0], s0);
        s1 = fmaf(g_part[((size_t)b * 32 + c + 1) * 256 + t], scale_s[c + 1], s1);
        s2 = fmaf(g_part[((size_t)b * 32 + c + 2) * 256 + t], scale_s[c + 2], s2);
        s3 = fmaf(g_part[((size_t)b * 32 + c + 3) * 256 + t], scale_s[c + 3], s3);
    }
    float s = (s0 + s1) + (s2 + s3);
    g_x2[b * K2H + 256 + t] = s;
    g_xT[(256 + t) * 32 + b] = s;
    // attention weights
    float m = stat_s[0], invZ = stat_s[1];
    #pragma unroll
    for (int j = 0; j < 8; j++) {
        int l = t + 256 * j;
        out[OUT_AW + b * LL + l] = expf(g_scores[b * LL + l] - m) * invZ;
    }
}

// ---------------- K4: LSTM gates GEMM, 4 g-rows/warp, 2-way K-split ----------------
__global__ void k_gates(const float* __restrict__ W_ih, const float* __restrict__ b_ih,
                        const float* __restrict__ W_hh, const float* __restrict__ b_hh) {
    int t = threadIdx.x;
    int lane = t & 31, w = t >> 5;
    int g0 = blockIdx.x * 32 + w * 4;
    int ks = blockIdx.y;
    float acc0 = 0, acc1 = 0, acc2 = 0, acc3 = 0;

    auto span = [&](int k_lo, int k_hi, const float* W, int rstride, int koff) {
        for (int k = k_lo; k < k_hi; k += 4) {
            float x0 = g_xT[(k + 0) * 32 + lane];
            float x1 = g_xT[(k + 1) * 32 + lane];
            float x2 = g_xT[(k + 2) * 32 + lane];
            float x3 = g_xT[(k + 3) * 32 + lane];
            float4 w0 = *(const float4*)(W + (size_t)(g0 + 0) * rstride + (k - koff));
            float4 w1 = *(const float4*)(W + (size_t)(g0 + 1) * rstride + (k - koff));
            float4 w2 = *(const float4*)(W + (size_t)(g0 + 2) * rstride + (k - koff));
            float4 w3 = *(const float4*)(W + (size_t)(g0 + 3) * rstride + (k - koff));
            acc0 = fmaf(w0.x, x0, fmaf(w0.y, x1, fmaf(w0.z, x2, fmaf(w0.w, x3, acc0))));
            acc1 = fmaf(w1.x, x0, fmaf(w1.y, x1, fmaf(w1.z, x2, fmaf(w1.w, x3, acc1))));
            acc2 = fmaf(w2.x, x0, fmaf(w2.y, x1, fmaf(w2.z, x2, fmaf(w2.w, x3, acc2))));
            acc3 = fmaf(w3.x, x0, fmaf(w3.y, x1, fmaf(w3.z, x2, fmaf(w3.w, x3, acc3))));
        }
    };
    if (ks == 0) {
        span(0, 384, W_ih, 512, 0);
        acc0 += b_ih[g0 + 0] + b_hh[g0 + 0];
        acc1 += b_ih[g0 + 1] + b_hh[g0 + 1];
        acc2 += b_ih[g0 + 2] + b_hh[g0 + 2];
        acc3 += b_ih[g0 + 3] + b_hh[g0 + 3];
    } else {
        span(384, 512, W_ih, 512, 0);
        span(512, 768, W_hh, 256, 512);
    }
    float* gp = g_gpart + ks * 32768;
    gp[(g0 + 0) * 32 + lane] = acc0;
    gp[(g0 + 1) * 32 + lane] = acc1;
    gp[(g0 + 2) * 32 + lane] = acc2;
    gp[(g0 + 3) * 32 + lane] = acc3;
}

// ---------------- K5: LSTM pointwise ----------------
__global__ void k_lstm(const float* __restrict__ cell, float* __restrict__ out) {
    int b = blockIdx.x, h = threadIdx.x;
    float ig = g_gpart[(0 * HH + h) * 32 + b] + g_gpart[32768 + (0 * HH + h) * 32 + b];
    float fg = g_gpart[(1 * HH + h) * 32 + b] + g_gpart[32768 + (1 * HH + h) * 32 + b];
    float gg = g_gpart[(2 * HH + h) * 32 + b] + g_gpart[32768 + (2 * HH + h) * 32 + b];
    float og = g_gpart[(3 * HH + h) * 32 + b] + g_gpart[32768 + (3 * HH + h) * 32 + b];
    float c_new = sigf(fg) * cell[b * HH + h] + sigf(ig) * tanhf(gg);
    float h_new = sigf(og) * tanhf(c_new);
    out[OUT_H + b * HH + h] = h_new;
    out[OUT_C + b * HH + h] = c_new;
    g_x2[b * K2H + h] = h_new;
}

// ---------------- K6: logits GEMM — f32x2 packed over even/odd k ----------------
// W smem stays row-major [v][k] (stride 34, conflict-free pairs), X [b][k]
// (stride 34 + XOR swizzle, conflict-free pairs, NO duplication).
// Per 2k-step per thread: 8 conflict-free LDS.64 for 16 FFMA2 (32 MACs).
#define WSD 34
__global__ void __launch_bounds__(256, 2) k_logits(const float* __restrict__ Wo,
                                                   const float* __restrict__ bo,
                                                   float* __restrict__ out) {
    __shared__ float Wt[2][128 * WSD];     // 2 x 17408 B
    __shared__ float Xs[2][32 * WSD + 8];  // 2 x ~4.3 KB

    int t = threadIdx.x;
    int v0 = blockIdx.x * 128;
    int vq = t >> 3, bq = t & 7;

    float4 wreg[4];
    float4 xreg;

    auto load_tile = [&](int kt) {
        #pragma unroll
        for (int jj = 0; jj < 4; jj++) {
            int idx = jj * 256 + t;
            int row = idx >> 3, q = idx & 7;
            int vr = v0 + row;
            wreg[jj] = (vr < VV) ? *(const float4*)(Wo + (size_t)vr * 512 + kt + 4 * q)
                                 : make_float4(0.f, 0.f, 0.f, 0.f);
        }
        xreg = *(const float4*)(g_x2 + (t >> 3) * K2H + kt + 4 * (t & 7));
    };
    auto store_tile = [&](int s) {
        #pragma unroll
        for (int jj = 0; jj < 4; jj++) {
            int idx = jj * 256 + t;
            int row = idx >> 3, q = idx & 7;
            float* p = &Wt[s][row * WSD + 4 * q];
            *(float2*)(p)     = make_float2(wreg[jj].x, wreg[jj].y);
            *(float2*)(p + 2) = make_float2(wreg[jj].z, wreg[jj].w);
        }
        int b = t >> 3, q = t & 7;
        float* p = &Xs[s][b * WSD + 4 * q + 2 * ((b >> 4) & 1)];
        *(float2*)(p)     = make_float2(xreg.x, xreg.y);
        *(float2*)(p + 2) = make_float2(xreg.z, xreg.w);
    };

    unsigned long long acc[4][4];
    #pragma unroll
    for (int i = 0; i < 4; i++)
        #pragma unroll
        for (int j = 0; j < 4; j++) acc[i][j] = 0ull;

    load_tile(0);
    store_tile(0);
    __syncthreads();

    for (int it = 0; it < 16; it++) {
        int cur = it & 1;
        if (it < 15) load_tile((it + 1) * 32);
        const float* W = Wt[cur];
        const float* X = Xs[cur];
        #pragma unroll
        for (int kk = 0; kk < 32; kk += 2) {
            unsigned long long wv[4], xv[4];
            #pragma unroll
            for (int i = 0; i < 4; i++)
                wv[i] = *(const unsigned long long*)(W + (vq * 4 + i) * WSD + kk);
            #pragma unroll
            for (int j = 0; j < 4; j++) {
                int bj = bq * 4 + j;
                xv[j] = *(const unsigned long long*)(X + bj * WSD + kk + 2 * ((bj >> 4) & 1));
            }
            #pragma unroll
            for (int i = 0; i < 4; i++)
                #pragma unroll
                for (int j = 0; j < 4; j++)
                    acc[i][j] = ffma2(wv[i], xv[j], acc[i][j]);
        }
        if (it < 15) store_tile(cur ^ 1);
        __syncthreads();
    }

    #pragma unroll
    for (int i = 0; i < 4; i++) {
        int vv = v0 + vq * 4 + i;
        if (vv < VV) {
            float bias = bo[vv];
            #pragma unroll
            for (int j = 0; j < 4; j++) {
                int bb = bq * 4 + j;
                float lo = __uint_as_float((unsigned)(acc[i][j] & 0xffffffffull));
                float hi = __uint_as_float((unsigned)(acc[i][j] >> 32));
                out[(size_t)bb * VV + vv] = (lo + hi) + bias;
            }
        }
    }
}

// ---------------- K7: per-b logsumexp over V (4-way MLP) ----------------
__global__ void k_lse(const float* __restrict__ out) {
    __shared__ float red[1024];
    int b = blockIdx.x, t = threadIdx.x;
    const float* p = out + (size_t)b * VV;
    float m0 = -1e30f, m1 = -1e30f, m2 = -1e30f, m3 = -1e30f;
    for (int i = t; i < VV; i += 4096) {
        m0 = fmaxf(m0, p[i]);
        if (i + 1024 < VV) m1 = fmaxf(m1, p[i + 1024]);
        if (i + 2048 < VV) m2 = fmaxf(m2, p[i + 2048]);
        if (i + 3072 < VV) m3 = fmaxf(m3, p[i + 3072]);
    }
    float m = fmaxf(fmaxf(m0, m1), fmaxf(m2, m3));
    red[t] = m; __syncthreads();
    for (int o = 512; o > 0; o >>= 1) { if (t < o) red[t] = fmaxf(red[t], red[t + o]); __syncthreads(); }
    m = red[0]; __syncthreads();
    float s0 = 0, s1 = 0, s2 = 0, s3 = 0;
    for (int i = t; i < VV; i += 4096) {
        s0 += expf(p[i] - m);
        if (i + 1024 < VV) s1 += expf(p[i + 1024] - m);
        if (i + 2048 < VV) s2 += expf(p[i + 2048] - m);
        if (i + 3072 < VV) s3 += expf(p[i + 3072] - m);
    }
    red[t] = (s0 + s1) + (s2 + s3); __syncthreads();
    for (int o = 512; o > 0; o >>= 1) { if (t < o) red[t] += red[t + o]; __syncthreads(); }
    if (t == 0) g_lse[b] = m + logf(red[0]);
}

// ---------------- K8: log_probs = logits - lse ----------------
__global__ void k_sub(float* __restrict__ out) {
    int b = blockIdx.y;
    int v = blockIdx.x * 256 + threadIdx.x;
    if (v < VV) out[(size_t)b * VV + v] -= g_lse[b];
}

extern "C" void kernel_launch(void* const* d_in, const int* in_sizes, int n_in,
                              void* d_out, int out_size) {
    const int*   tokens    = (const int*)d_in[0];
    const float* hidden    = (const float*)d_in[1];
    const float* cell      = (const float*)d_in[2];
    const float* enc       = (const float*)d_in[3];
    const float* emb_table = (const float*)d_in[4];
    const float* W_attn    = (const float*)d_in[5];
    // d_in[6] = b_attn unused (softmax shift-invariance)
    const float* vvec      = (const float*)d_in[7];
    const float* W_ih      = (const float*)d_in[8];
    const float* b_ih      = (const float*)d_in[9];
    const float* W_hh      = (const float*)d_in[10];
    const float* b_hh      = (const float*)d_in[11];
    const float* W_out     = (const float*)d_in[12];
    const float* b_out     = (const float*)d_in[13];
    float* out = (float*)d_out;

    // Idempotent; not a stream op (not captured into the graph).
    cudaFuncSetAttribute(kA, cudaFuncAttributeMaxDynamicSharedMemorySize, 65536);

    k_init<<<36, 256>>>(tokens, emb_table, hidden, W_attn, vvec);       // 1
    {
        dim3 g(32, BB);
        kA<<<g, 256, 65536>>>(enc);                                      // 2
    }
    kB<<<BB, 256>>>(out);                                                // 3
    {
        dim3 g(32, 2);
        k_gates<<<g, 256>>>(W_ih, b_ih, W_hh, b_hh);                     // 4
    }
    k_lstm<<<BB, 256>>>(cell, out);                                      // 5
    k_logits<<<(VV + 127) / 128, 256>>>(W_out, b_out, out);              // 6 <- profiled (-s 5)
    k_lse<<<BB, 1024>>>(out);                                            // 7
    {
        dim3 g((VV + 255) / 256, BB);
        k_sub<<<g, 256>>>(out);                                          // 8
    }
}

// round 9
// speedup vs baseline: 2.0622x; 1.2765x over previous
#include <cuda_runtime.h>
#include <math.h>

#define BB 32
#define HH 256
#define LL 2048
#define VV 50257
#define K2H 512
#define NBLK 393          // ceil(VV/128)
#define NKS 8             // k-splits for gates

// d_out layout: log_probs[B*V], h_new[B*H], c_new[B*H], attn_weights[B*L]
#define OUT_H  (BB * VV)
#define OUT_C  (OUT_H + BB * HH)
#define OUT_AW (OUT_C + BB * HH)

// ---------------- scratch ----------------
__device__ __align__(16) float g_wpart[4 * 256];       // partial We^T v
__device__ __align__(16) float g_scores[BB * LL];
__device__ __align__(16) float g_ms[BB * 32];          // per-chunk max
__device__ __align__(16) float g_Ss[BB * 32];          // per-chunk expsum
__device__ __align__(16) float g_part[BB * 32 * HH];   // per-chunk weighted partials
__device__ __align__(16) float g_xT[768 * 32];         // [k][b] LSTM input transposed
__device__ __align__(16) float g_gpart[NKS * 1024 * 32]; // gate partials [ks][g][b]
__device__ __align__(16) float g_x2[BB * K2H];         // concat(h_new, attnap) per b
__device__ __align__(16) float g_lsem[NBLK * 32];      // per-vblock max per b
__device__ __align__(16) float g_lses[NBLK * 32];      // per-vblock expsum per b
__device__ float g_lse[BB];

static __device__ __forceinline__ unsigned long long ffma2(
    unsigned long long a, unsigned long long b, unsigned long long c) {
    unsigned long long d;
    asm("fma.rn.f32x2 %0, %1, %2, %3;" : "=l"(d) : "l"(a), "l"(b), "l"(c));
    return d;
}

static __device__ __forceinline__ float sigf(float x) { return 1.0f / (1.0f + expf(-x)); }

// ---------------- K1: init — w partials (blocks 0-3), emb+hidden transpose (blocks 4-35) ----
__global__ void k_init(const int* __restrict__ tokens,
                       const float* __restrict__ emb_table,
                       const float* __restrict__ hidden,
                       const float* __restrict__ W_attn,
                       const float* __restrict__ vvec) {
    int t = threadIdx.x;
    if (blockIdx.x < 4) {
        int kb = blockIdx.x * 64;
        float a0 = 0, a1 = 0, a2 = 0, a3 = 0;
        #pragma unroll 4
        for (int i = 0; i < 64; i += 4) {
            a0 = fmaf(vvec[kb + i + 0], W_attn[(kb + i + 0) * 512 + 256 + t], a0);
            a1 = fmaf(vvec[kb + i + 1], W_attn[(kb + i + 1) * 512 + 256 + t], a1);
            a2 = fmaf(vvec[kb + i + 2], W_attn[(kb + i + 2) * 512 + 256 + t], a2);
            a3 = fmaf(vvec[kb + i + 3], W_attn[(kb + i + 3) * 512 + 256 + t], a3);
        }
        g_wpart[blockIdx.x * 256 + t] = (a0 + a1) + (a2 + a3);
    } else {
        int b = blockIdx.x - 4;
        int tok = tokens[b];
        g_xT[t * 32 + b] = emb_table[(long long)tok * HH + t];
        g_xT[(512 + t) * 32 + b] = hidden[b * HH + t];
    }
}

// ---------------- K2: fused attention pass 1 — per (chunk c, batch b) ----------------
__global__ void kA(const float* __restrict__ enc) {
    extern __shared__ float es[];       // 64*256 floats = 64 KB
    __shared__ float w_s[256];
    __shared__ float score_s[64];
    __shared__ float esc_s[64];
    __shared__ float mred_s[1];
    int c = blockIdx.x, b = blockIdx.y;
    int t = threadIdx.x;
    int lane = t & 31, wid = t >> 5;

    w_s[t] = g_wpart[t] + g_wpart[256 + t] + g_wpart[512 + t] + g_wpart[768 + t];

    const float4* e4 = (const float4*)(enc + ((size_t)b * LL + c * 64) * HH);
    float4* s4 = (float4*)es;
    #pragma unroll
    for (int i = 0; i < 16; i++) s4[t + 256 * i] = e4[t + 256 * i];
    __syncthreads();

    const float4* w4 = (const float4*)w_s;
    float4 wa = w4[lane], wb = w4[32 + lane];
    #pragma unroll
    for (int r = wid; r < 64; r += 8) {
        const float4* row = (const float4*)(es + r * 256);
        float4 a = row[lane], cc = row[32 + lane];
        float s = a.x * wa.x + a.y * wa.y + a.z * wa.z + a.w * wa.w
                + cc.x * wb.x + cc.y * wb.y + cc.z * wb.z + cc.w * wb.w;
        #pragma unroll
        for (int off = 16; off > 0; off >>= 1)
            s += __shfl_xor_sync(0xffffffffu, s, off);
        if (lane == 0) {
            score_s[r] = s;
            g_scores[b * LL + c * 64 + r] = s;
        }
    }
    __syncthreads();

    if (t < 32) {
        float m = fmaxf(score_s[t], score_s[t + 32]);
        #pragma unroll
        for (int off = 16; off > 0; off >>= 1)
            m = fmaxf(m, __shfl_xor_sync(0xffffffffu, m, off));
        if (lane == 0) mred_s[0] = m;
    }
    __syncthreads();
    float m_c = mred_s[0];
    if (t < 64) esc_s[t] = expf(score_s[t] - m_c);
    __syncthreads();
    if (t < 32) {
        float sum = esc_s[t] + esc_s[t + 32];
        #pragma unroll
        for (int off = 16; off > 0; off >>= 1)
            sum += __shfl_xor_sync(0xffffffffu, sum, off);
        if (lane == 0) { g_ms[b * 32 + c] = m_c; g_Ss[b * 32 + c] = sum; }
    }

    float a0 = 0, a1 = 0, a2 = 0, a3 = 0;
    #pragma unroll
    for (int l = 0; l < 64; l += 4) {
        a0 = fmaf(esc_s[l + 0], es[(l + 0) * 256 + t], a0);
        a1 = fmaf(esc_s[l + 1], es[(l + 1) * 256 + t], a1);
        a2 = fmaf(esc_s[l + 2], es[(l + 2) * 256 + t], a2);
        a3 = fmaf(esc_s[l + 3], es[(l + 3) * 256 + t], a3);
    }
    g_part[((size_t)b * 32 + c) * 256 + t] = (a0 + a1) + (a2 + a3);
}

// ---------------- K3: attention combine — global stats, weights, attn_applied ----------------
__global__ void kB(float* __restrict__ out) {
    __shared__ float scale_s[32];
    __shared__ float stat_s[2];
    int b = blockIdx.x, t = threadIdx.x;
    if (t < 32) {
        float mc = g_ms[b * 32 + t];
        float m = mc;
        #pragma unroll
        for (int off = 16; off > 0; off >>= 1)
            m = fmaxf(m, __shfl_xor_sync(0xffffffffu, m, off));
        float e = expf(mc - m);
        float z = g_Ss[b * 32 + t] * e;
        #pragma unroll
        for (int off = 16; off > 0; off >>= 1)
            z += __shfl_xor_sync(0xffffffffu, z, off);
        scale_s[t] = e / z;
        if (t == 0) { stat_s[0] = m; stat_s[1] = 1.0f / z; }
    }
    __syncthreads();
    float s0 = 0, s1 = 0, s2 = 0, s3 = 0;
    #pragma unroll
    for (int c = 0; c < 32; c += 4) {
        s0 = fmaf(g_part[((size_t)b * 32 + c + 0) * 256 + t], scale_s[c + 0], s0);
        s1 = fmaf(g_part[((size_t)b * 32 + c + 1) * 256 + t], scale_s[c + 1], s1);
        s2 = fmaf(g_part[((size_t)b * 32 + c + 2) * 256 + t], scale_s[c + 2], s2);
        s3 = fmaf(g_part[((size_t)b * 32 + c + 3) * 256 + t], scale_s[c + 3], s3);
    }
    float s = (s0 + s1) + (s2 + s3);
    g_x2[b * K2H + 256 + t] = s;
    g_xT[(256 + t) * 32 + b] = s;
    float m = stat_s[0], invZ = stat_s[1];
    #pragma unroll
    for (int j = 0; j < 8; j++) {
        int l = t + 256 * j;
        out[OUT_AW + b * LL + l] = expf(g_scores[b * LL + l] - m) * invZ;
    }
}

// ---------------- K4: LSTM gates GEMM, 4 g-rows/warp, 8-way K-split ----------------
__global__ void k_gates(const float* __restrict__ W_ih, const float* __restrict__ b_ih,
                        const float* __restrict__ W_hh, const float* __restrict__ b_hh) {
    int t = threadIdx.x;
    int lane = t & 31, w = t >> 5;
    int g0 = blockIdx.x * 32 + w * 4;
    int ks = blockIdx.y;
    int klo = ks * 96, khi = klo + 96;
    float acc0 = 0, acc1 = 0, acc2 = 0, acc3 = 0;

    auto span = [&](int k_lo, int k_hi, const float* W, int rstride, int koff) {
        #pragma unroll 2
        for (int k = k_lo; k < k_hi; k += 4) {
            float x0 = g_xT[(k + 0) * 32 + lane];
            float x1 = g_xT[(k + 1) * 32 + lane];
            float x2 = g_xT[(k + 2) * 32 + lane];
            float x3 = g_xT[(k + 3) * 32 + lane];
            float4 w0 = *(const float4*)(W + (size_t)(g0 + 0) * rstride + (k - koff));
            float4 w1 = *(const float4*)(W + (size_t)(g0 + 1) * rstride + (k - koff));
            float4 w2 = *(const float4*)(W + (size_t)(g0 + 2) * rstride + (k - koff));
            float4 w3 = *(const float4*)(W + (size_t)(g0 + 3) * rstride + (k - koff));
            acc0 = fmaf(w0.x, x0, fmaf(w0.y, x1, fmaf(w0.z, x2, fmaf(w0.w, x3, acc0))));
            acc1 = fmaf(w1.x, x0, fmaf(w1.y, x1, fmaf(w1.z, x2, fmaf(w1.w, x3, acc1))));
            acc2 = fmaf(w2.x, x0, fmaf(w2.y, x1, fmaf(w2.z, x2, fmaf(w2.w, x3, acc2))));
            acc3 = fmaf(w3.x, x0, fmaf(w3.y, x1, fmaf(w3.z, x2, fmaf(w3.w, x3, acc3))));
        }
    };
    if (klo < 512)  span(klo, khi < 512 ? khi : 512, W_ih, 512, 0);
    if (khi > 512)  span(klo > 512 ? klo : 512, khi, W_hh, 256, 512);
    if (ks == 0) {
        acc0 += b_ih[g0 + 0] + b_hh[g0 + 0];
        acc1 += b_ih[g0 + 1] + b_hh[g0 + 1];
        acc2 += b_ih[g0 + 2] + b_hh[g0 + 2];
        acc3 += b_ih[g0 + 3] + b_hh[g0 + 3];
    }
    float* gp = g_gpart + ks * 32768;
    gp[(g0 + 0) * 32 + lane] = acc0;
    gp[(g0 + 1) * 32 + lane] = acc1;
    gp[(g0 + 2) * 32 + lane] = acc2;
    gp[(g0 + 3) * 32 + lane] = acc3;
}

// ---------------- K5: LSTM pointwise (sums 8 k-split partials) ----------------
__global__ void k_lstm(const float* __restrict__ cell, float* __restrict__ out) {
    int b = blockIdx.x, h = threadIdx.x;
    float ig = 0, fg = 0, gg = 0, og = 0;
    #pragma unroll
    for (int ks = 0; ks < NKS; ks++) {
        const float* gp = g_gpart + ks * 32768;
        ig += gp[(0 * HH + h) * 32 + b];
        fg += gp[(1 * HH + h) * 32 + b];
        gg += gp[(2 * HH + h) * 32 + b];
        og += gp[(3 * HH + h) * 32 + b];
    }
    float c_new = sigf(fg) * cell[b * HH + h] + sigf(ig) * tanhf(gg);
    float h_new = sigf(og) * tanhf(c_new);
    out[OUT_H + b * HH + h] = h_new;
    out[OUT_C + b * HH + h] = c_new;
    g_x2[b * K2H + h] = h_new;
}

// ---------------- K6: logits GEMM — f32x2 packed over even/odd k + per-block LSE partials ----
#define WSD 34
__global__ void __launch_bounds__(256, 2) k_logits(const float* __restrict__ Wo,
                                                   const float* __restrict__ bo,
                                                   float* __restrict__ out) {
    __shared__ float Wt[2][128 * WSD];
    __shared__ float Xs[2][32 * WSD + 8];
    __shared__ float red[32 * 32];        // [vq][b] reduction scratch

    int t = threadIdx.x;
    int v0 = blockIdx.x * 128;
    int vq = t >> 3, bq = t & 7;

    float4 wreg[4];
    float4 xreg;

    auto load_tile = [&](int kt) {
        #pragma unroll
        for (int jj = 0; jj < 4; jj++) {
            int idx = jj * 256 + t;
            int row = idx >> 3, q = idx & 7;
            int vr = v0 + row;
            wreg[jj] = (vr < VV) ? *(const float4*)(Wo + (size_t)vr * 512 + kt + 4 * q)
                                 : make_float4(0.f, 0.f, 0.f, 0.f);
        }
        xreg = *(const float4*)(g_x2 + (t >> 3) * K2H + kt + 4 * (t & 7));
    };
    auto store_tile = [&](int s) {
        #pragma unroll
        for (int jj = 0; jj < 4; jj++) {
            int idx = jj * 256 + t;
            int row = idx >> 3, q = idx & 7;
            float* p = &Wt[s][row * WSD + 4 * q];
            *(float2*)(p)     = make_float2(wreg[jj].x, wreg[jj].y);
            *(float2*)(p + 2) = make_float2(wreg[jj].z, wreg[jj].w);
        }
        int b = t >> 3, q = t & 7;
        float* p = &Xs[s][b * WSD + 4 * q + 2 * ((b >> 4) & 1)];
        *(float2*)(p)     = make_float2(xreg.x, xreg.y);
        *(float2*)(p + 2) = make_float2(xreg.z, xreg.w);
    };

    unsigned long long acc[4][4];
    #pragma unroll
    for (int i = 0; i < 4; i++)
        #pragma unroll
        for (int j = 0; j < 4; j++) acc[i][j] = 0ull;

    load_tile(0);
    store_tile(0);
    __syncthreads();

    for (int it = 0; it < 16; it++) {
        int cur = it & 1;
        if (it < 15) load_tile((it + 1) * 32);
        const float* W = Wt[cur];
        const float* X = Xs[cur];
        #pragma unroll
        for (int kk = 0; kk < 32; kk += 2) {
            unsigned long long wv[4], xv[4];
            #pragma unroll
            for (int i = 0; i < 4; i++)
                wv[i] = *(const unsigned long long*)(W + (vq * 4 + i) * WSD + kk);
            #pragma unroll
            for (int j = 0; j < 4; j++) {
                int bj = bq * 4 + j;
                xv[j] = *(const unsigned long long*)(X + bj * WSD + kk + 2 * ((bj >> 4) & 1));
            }
            #pragma unroll
            for (int i = 0; i < 4; i++)
                #pragma unroll
                for (int j = 0; j < 4; j++)
                    acc[i][j] = ffma2(wv[i], xv[j], acc[i][j]);
        }
        if (it < 15) store_tile(cur ^ 1);
        __syncthreads();
    }

    // finalize logits into registers, write out, track per-thread max
    float lg[4][4];
    float lmax[4] = { -1e30f, -1e30f, -1e30f, -1e30f };
    #pragma unroll
    for (int i = 0; i < 4; i++) {
        int vv = v0 + vq * 4 + i;
        if (vv < VV) {
            float bias = bo[vv];
            #pragma unroll
            for (int j = 0; j < 4; j++) {
                float lo = __uint_as_float((unsigned)(acc[i][j] & 0xffffffffull));
                float hi = __uint_as_float((unsigned)(acc[i][j] >> 32));
                float l = (lo + hi) + bias;
                lg[i][j] = l;
                lmax[j] = fmaxf(lmax[j], l);
                out[(size_t)(bq * 4 + j) * VV + vv] = l;
            }
        } else {
            #pragma unroll
            for (int j = 0; j < 4; j++) lg[i][j] = -1e30f;
        }
    }

    // block-level per-b max over vq
    #pragma unroll
    for (int j = 0; j < 4; j++) red[vq * 32 + bq * 4 + j] = lmax[j];
    __syncthreads();
    for (int off = 16; off > 0; off >>= 1) {
        if (vq < off) {
            #pragma unroll
            for (int j = 0; j < 4; j++) {
                int b = bq * 4 + j;
                red[vq * 32 + b] = fmaxf(red[vq * 32 + b], red[(vq + off) * 32 + b]);
            }
        }
        __syncthreads();
    }
    float mb[4];
    #pragma unroll
    for (int j = 0; j < 4; j++) mb[j] = red[bq * 4 + j];
    __syncthreads();

    // block-level per-b expsum
    float lsum[4] = { 0.f, 0.f, 0.f, 0.f };
    #pragma unroll
    for (int i = 0; i < 4; i++)
        #pragma unroll
        for (int j = 0; j < 4; j++)
            if (lg[i][j] > -1e29f) lsum[j] += expf(lg[i][j] - mb[j]);
    #pragma unroll
    for (int j = 0; j < 4; j++) red[vq * 32 + bq * 4 + j] = lsum[j];
    __syncthreads();
    for (int off = 16; off > 0; off >>= 1) {
        if (vq < off) {
            #pragma unroll
            for (int j = 0; j < 4; j++) {
                int b = bq * 4 + j;
                red[vq * 32 + b] += red[(vq + off) * 32 + b];
            }
        }
        __syncthreads();
    }
    if (vq == 0) {
        #pragma unroll
        for (int j = 0; j < 4; j++) {
            int b = bq * 4 + j;
            g_lsem[blockIdx.x * 32 + b] = mb[j];
            g_lses[blockIdx.x * 32 + b] = red[b];
        }
    }
}

// ---------------- K7: merge per-block LSE partials ----------------
__global__ void k_lse() {
    __shared__ float mred[512], sred[512];
    int b = blockIdx.x, t = threadIdx.x;
    float m = -1e30f, S = 0.f;
    if (t < NBLK) {
        m = g_lsem[t * 32 + b];
        S = g_lses[t * 32 + b];
    }
    mred[t] = m; sred[t] = S;
    __syncthreads();
    for (int off = 256; off > 0; off >>= 1) {
        if (t < off) {
            float m1 = mred[t], m2 = mred[t + off];
            float s1 = sred[t], s2 = sred[t + off];
            float mm = fmaxf(m1, m2);
            mred[t] = mm;
            sred[t] = s1 * expf(m1 - mm) + s2 * expf(m2 - mm);
        }
        __syncthreads();
    }
    if (t == 0) g_lse[b] = mred[0] + logf(sred[0]);
}

// ---------------- K8: log_probs = logits - lse ----------------
__global__ void k_sub(float* __restrict__ out) {
    int b = blockIdx.y;
    int v = blockIdx.x * 256 + threadIdx.x;
    if (v < VV) out[(size_t)b * VV + v] -= g_lse[b];
}

extern "C" void kernel_launch(void* const* d_in, const int* in_sizes, int n_in,
                              void* d_out, int out_size) {
    const int*   tokens    = (const int*)d_in[0];
    const float* hidden    = (const float*)d_in[1];
    const float* cell      = (const float*)d_in[2];
    const float* enc       = (const float*)d_in[3];
    const float* emb_table = (const float*)d_in[4];
    const float* W_attn    = (const float*)d_in[5];
    // d_in[6] = b_attn unused (softmax shift-invariance)
    const float* vvec      = (const float*)d_in[7];
    const float* W_ih      = (const float*)d_in[8];
    const float* b_ih      = (const float*)d_in[9];
    const float* W_hh      = (const float*)d_in[10];
    const float* b_hh      = (const float*)d_in[11];
    const float* W_out     = (const float*)d_in[12];
    const float* b_out     = (const float*)d_in[13];
    float* out = (float*)d_out;

    // Idempotent; not a stream op (not captured into the graph).
    cudaFuncSetAttribute(kA, cudaFuncAttributeMaxDynamicSharedMemorySize, 65536);

    k_init<<<36, 256>>>(tokens, emb_table, hidden, W_attn, vvec);       // 1
    {
        dim3 g(32, BB);
        kA<<<g, 256, 65536>>>(enc);                                      // 2
    }
    kB<<<BB, 256>>>(out);                                                // 3
    {
        dim3 g(32, NKS);
        k_gates<<<g, 256>>>(W_ih, b_ih, W_hh, b_hh);                     // 4
    }
    k_lstm<<<BB, 256>>>(cell, out);                                      // 5
    k_logits<<<NBLK, 256>>>(W_out, b_out, out);                          // 6 <- profiled (-s 5)
    k_lse<<<BB, 512>>>();                                                // 7
    {
        dim3 g((VV + 255) / 256, BB);
        k_sub<<<g, 256>>>(out);                                          // 8
    }
}

// round 10
// speedup vs baseline: 2.2340x; 1.0833x over previous
#include <cuda_runtime.h>
#include <math.h>

#define BB 32
#define HH 256
#define LL 2048
#define VV 50257
#define K2H 512
#define NBLK 393          // ceil(VV/128)
#define NKS 8             // k-splits for gates
#define NCH 64            // attention l-chunks (32 rows each)

// d_out layout: log_probs[B*V], h_new[B*H], c_new[B*H], attn_weights[B*L]
#define OUT_H  (BB * VV)
#define OUT_C  (OUT_H + BB * HH)
#define OUT_AW (OUT_C + BB * HH)

// ---------------- scratch ----------------
__device__ __align__(16) float g_wpart[4 * 256];        // partial We^T v
__device__ __align__(16) float g_scores[BB * LL];
__device__ __align__(16) float g_ms[BB * NCH];          // per-chunk max
__device__ __align__(16) float g_Ss[BB * NCH];          // per-chunk expsum
__device__ __align__(16) float g_part[BB * NCH * HH];   // per-chunk weighted partials
__device__ __align__(16) float g_xT[768 * 32];          // [k][b] LSTM input transposed
__device__ __align__(16) float g_gpart[NKS * 1024 * 32];// gate partials [ks][g][b]
__device__ __align__(16) float g_x2[BB * K2H];          // concat(h_new, attnap) per b
__device__ __align__(16) float g_lsem[NBLK * 32];       // per-vblock max per b
__device__ __align__(16) float g_lses[NBLK * 32];       // per-vblock expsum per b
__device__ float g_lse[BB];

static __device__ __forceinline__ unsigned long long ffma2(
    unsigned long long a, unsigned long long b, unsigned long long c) {
    unsigned long long d;
    asm("fma.rn.f32x2 %0, %1, %2, %3;" : "=l"(d) : "l"(a), "l"(b), "l"(c));
    return d;
}

static __device__ __forceinline__ float sigf(float x) { return 1.0f / (1.0f + expf(-x)); }

// ---------------- K1: init — w partials (blocks 0-3), emb+hidden transpose (blocks 4-35) ----
__global__ void k_init(const int* __restrict__ tokens,
                       const float* __restrict__ emb_table,
                       const float* __restrict__ hidden,
                       const float* __restrict__ W_attn,
                       const float* __restrict__ vvec) {
    int t = threadIdx.x;
    if (blockIdx.x < 4) {
        int kb = blockIdx.x * 64;
        float a0 = 0, a1 = 0, a2 = 0, a3 = 0;
        #pragma unroll 4
        for (int i = 0; i < 64; i += 4) {
            a0 = fmaf(vvec[kb + i + 0], W_attn[(kb + i + 0) * 512 + 256 + t], a0);
            a1 = fmaf(vvec[kb + i + 1], W_attn[(kb + i + 1) * 512 + 256 + t], a1);
            a2 = fmaf(vvec[kb + i + 2], W_attn[(kb + i + 2) * 512 + 256 + t], a2);
            a3 = fmaf(vvec[kb + i + 3], W_attn[(kb + i + 3) * 512 + 256 + t], a3);
        }
        g_wpart[blockIdx.x * 256 + t] = (a0 + a1) + (a2 + a3);
    } else {
        int b = blockIdx.x - 4;
        int tok = tokens[b];
        g_xT[t * 32 + b] = emb_table[(long long)tok * HH + t];
        g_xT[(512 + t) * 32 + b] = hidden[b * HH + t];
    }
}

// ---------------- K2: fused attention pass 1 — per (chunk c, batch b), 32 rows/chunk ------
__global__ void kA(const float* __restrict__ enc) {
    __shared__ float es[32 * 256];      // 32 KB -> ~7 blocks/SM
    __shared__ float w_s[256];
    __shared__ float score_s[32];
    __shared__ float esc_s[32];
    __shared__ float mred_s[1];
    int c = blockIdx.x, b = blockIdx.y;
    int t = threadIdx.x;
    int lane = t & 31, wid = t >> 5;

    w_s[t] = g_wpart[t] + g_wpart[256 + t] + g_wpart[512 + t] + g_wpart[768 + t];

    const float4* e4 = (const float4*)(enc + ((size_t)b * LL + c * 32) * HH);
    float4* s4 = (float4*)es;
    #pragma unroll
    for (int i = 0; i < 8; i++) s4[t + 256 * i] = e4[t + 256 * i];
    __syncthreads();

    const float4* w4 = (const float4*)w_s;
    float4 wa = w4[lane], wb = w4[32 + lane];
    #pragma unroll
    for (int r = wid; r < 32; r += 8) {
        const float4* row = (const float4*)(es + r * 256);
        float4 a = row[lane], cc = row[32 + lane];
        float s = a.x * wa.x + a.y * wa.y + a.z * wa.z + a.w * wa.w
                + cc.x * wb.x + cc.y * wb.y + cc.z * wb.z + cc.w * wb.w;
        #pragma unroll
        for (int off = 16; off > 0; off >>= 1)
            s += __shfl_xor_sync(0xffffffffu, s, off);
        if (lane == 0) {
            score_s[r] = s;
            g_scores[b * LL + c * 32 + r] = s;
        }
    }
    __syncthreads();

    if (t < 32) {
        float m = score_s[t];
        #pragma unroll
        for (int off = 16; off > 0; off >>= 1)
            m = fmaxf(m, __shfl_xor_sync(0xffffffffu, m, off));
        if (lane == 0) mred_s[0] = m;
        __syncwarp();
        float m_c = mred_s[0];
        float e = expf(score_s[t] - m_c);
        esc_s[t] = e;
        float sum = e;
        #pragma unroll
        for (int off = 16; off > 0; off >>= 1)
            sum += __shfl_xor_sync(0xffffffffu, sum, off);
        if (lane == 0) { g_ms[b * NCH + c] = m_c; g_Ss[b * NCH + c] = sum; }
    }
    __syncthreads();

    float a0 = 0, a1 = 0, a2 = 0, a3 = 0;
    #pragma unroll
    for (int l = 0; l < 32; l += 4) {
        a0 = fmaf(esc_s[l + 0], es[(l + 0) * 256 + t], a0);
        a1 = fmaf(esc_s[l + 1], es[(l + 1) * 256 + t], a1);
        a2 = fmaf(esc_s[l + 2], es[(l + 2) * 256 + t], a2);
        a3 = fmaf(esc_s[l + 3], es[(l + 3) * 256 + t], a3);
    }
    g_part[((size_t)b * NCH + c) * 256 + t] = (a0 + a1) + (a2 + a3);
}

// ---------------- K3: attention combine — global stats, weights, attn_applied ----------------
__global__ void kB(float* __restrict__ out) {
    __shared__ float mc_s[NCH], Ss_s[NCH], mred[NCH], scale_s[NCH];
    __shared__ float stat_s[2];
    int b = blockIdx.x, t = threadIdx.x;
    if (t < NCH) {
        mc_s[t] = g_ms[b * NCH + t];
        Ss_s[t] = g_Ss[b * NCH + t];
        mred[t] = mc_s[t];
    }
    __syncthreads();
    for (int off = NCH / 2; off > 0; off >>= 1) {
        if (t < off) mred[t] = fmaxf(mred[t], mred[t + off]);
        __syncthreads();
    }
    float m = mred[0];
    if (t < NCH) {
        float e = expf(mc_s[t] - m);
        scale_s[t] = e;           // pre-normalization
        mred[t] = Ss_s[t] * e;    // z partial
    }
    __syncthreads();
    for (int off = NCH / 2; off > 0; off >>= 1) {
        if (t < off) mred[t] += mred[t + off];
        __syncthreads();
    }
    float invZ = 1.0f / mred[0];
    if (t == 0) { stat_s[0] = m; stat_s[1] = invZ; }
    if (t < NCH) scale_s[t] *= invZ;
    __syncthreads();

    // attn_applied for h = t
    float s0 = 0, s1 = 0, s2 = 0, s3 = 0;
    #pragma unroll
    for (int c = 0; c < NCH; c += 4) {
        s0 = fmaf(g_part[((size_t)b * NCH + c + 0) * 256 + t], scale_s[c + 0], s0);
        s1 = fmaf(g_part[((size_t)b * NCH + c + 1) * 256 + t], scale_s[c + 1], s1);
        s2 = fmaf(g_part[((size_t)b * NCH + c + 2) * 256 + t], scale_s[c + 2], s2);
        s3 = fmaf(g_part[((size_t)b * NCH + c + 3) * 256 + t], scale_s[c + 3], s3);
    }
    float s = (s0 + s1) + (s2 + s3);
    g_x2[b * K2H + 256 + t] = s;
    g_xT[(256 + t) * 32 + b] = s;

    // attention weights, float4 in/out (16B-aligned: OUT_AW%4==0, b*LL%4==0, t*8%4==0)
    float mm = stat_s[0], iz = stat_s[1];
    const float4* sc4 = (const float4*)(g_scores + b * LL + t * 8);
    float4* o4 = (float4*)(out + OUT_AW + b * LL + t * 8);
    float4 v0 = sc4[0], v1 = sc4[1];
    float4 r0, r1;
    r0.x = expf(v0.x - mm) * iz; r0.y = expf(v0.y - mm) * iz;
    r0.z = expf(v0.z - mm) * iz; r0.w = expf(v0.w - mm) * iz;
    r1.x = expf(v1.x - mm) * iz; r1.y = expf(v1.y - mm) * iz;
    r1.z = expf(v1.z - mm) * iz; r1.w = expf(v1.w - mm) * iz;
    o4[0] = r0; o4[1] = r1;
}

// ---------------- K4: LSTM gates GEMM — smem-tiled, coalesced ----------------
#define GT 64
#define KT 96
__global__ void k_gates(const float* __restrict__ W_ih, const float* __restrict__ b_ih,
                        const float* __restrict__ W_hh, const float* __restrict__ b_hh) {
    __shared__ float Ws[GT * KT];   // 24 KB  [g][k]
    __shared__ float xs[KT * 32];   // 12 KB  [k][b]
    int t = threadIdx.x;
    int g0 = blockIdx.x * GT;
    int ks = blockIdx.y;
    int klo = ks * KT;

    // stage W tile (coalesced; MLP=24)
    #pragma unroll
    for (int i = 0; i < GT * KT / 256; i++) {
        int idx = t + i * 256;
        int g = idx / KT, kk = idx - g * KT;
        int kg = klo + kk;
        float v = (kg < 512) ? W_ih[(size_t)(g0 + g) * 512 + kg]
                             : W_hh[(size_t)(g0 + g) * 256 + (kg - 512)];
        Ws[g * KT + kk] = v;
    }
    // stage x tile (coalesced; MLP=12)
    #pragma unroll
    for (int i = 0; i < KT * 32 / 256; i++) {
        int idx = t + i * 256;
        xs[idx] = g_xT[klo * 32 + idx];
    }
    __syncthreads();

    int lane = t & 31, w = t >> 5;
    int gl = w * 8;
    float acc[8] = {0, 0, 0, 0, 0, 0, 0, 0};
    #pragma unroll 4
    for (int kk = 0; kk < KT; kk += 2) {
        float x0 = xs[kk * 32 + lane];
        float x1 = xs[(kk + 1) * 32 + lane];
        #pragma unroll
        for (int g = 0; g < 8; g++) {
            float2 wp = *(const float2*)&Ws[(gl + g) * KT + kk];
            acc[g] = fmaf(wp.x, x0, fmaf(wp.y, x1, acc[g]));
        }
    }
    float* gp = g_gpart + ks * 32768;
    #pragma unroll
    for (int g = 0; g < 8; g++) {
        float a = acc[g];
        int gr = g0 + gl + g;
        if (ks == 0) a += b_ih[gr] + b_hh[gr];
        gp[gr * 32 + lane] = a;
    }
}

// ---------------- K5: LSTM pointwise (sums 8 k-split partials) ----------------
__global__ void k_lstm(const float* __restrict__ cell, float* __restrict__ out) {
    int b = blockIdx.x, h = threadIdx.x;
    float ig = 0, fg = 0, gg = 0, og = 0;
    #pragma unroll
    for (int ks = 0; ks < NKS; ks++) {
        const float* gp = g_gpart + ks * 32768;
        ig += gp[(0 * HH + h) * 32 + b];
        fg += gp[(1 * HH + h) * 32 + b];
        gg += gp[(2 * HH + h) * 32 + b];
        og += gp[(3 * HH + h) * 32 + b];
    }
    float c_new = sigf(fg) * cell[b * HH + h] + sigf(ig) * tanhf(gg);
    float h_new = sigf(og) * tanhf(c_new);
    out[OUT_H + b * HH + h] = h_new;
    out[OUT_C + b * HH + h] = c_new;
    g_x2[b * K2H + h] = h_new;
}

// ---------------- K6: logits GEMM — f32x2 packed over even/odd k + per-block LSE partials ----
#define WSD 34
__global__ void __launch_bounds__(256, 2) k_logits(const float* __restrict__ Wo,
                                                   const float* __restrict__ bo,
                                                   float* __restrict__ out) {
    __shared__ float Wt[2][128 * WSD];
    __shared__ float Xs[2][32 * WSD + 8];
    __shared__ float red[32 * 32];        // [vq][b] reduction scratch

    int t = threadIdx.x;
    int v0 = blockIdx.x * 128;
    int vq = t >> 3, bq = t & 7;

    float4 wreg[4];
    float4 xreg;

    auto load_tile = [&](int kt) {
        #pragma unroll
        for (int jj = 0; jj < 4; jj++) {
            int idx = jj * 256 + t;
            int row = idx >> 3, q = idx & 7;
            int vr = v0 + row;
            wreg[jj] = (vr < VV) ? *(const float4*)(Wo + (size_t)vr * 512 + kt + 4 * q)
                                 : make_float4(0.f, 0.f, 0.f, 0.f);
        }
        xreg = *(const float4*)(g_x2 + (t >> 3) * K2H + kt + 4 * (t & 7));
    };
    auto store_tile = [&](int s) {
        #pragma unroll
        for (int jj = 0; jj < 4; jj++) {
            int idx = jj * 256 + t;
            int row = idx >> 3, q = idx & 7;
            float* p = &Wt[s][row * WSD + 4 * q];
            *(float2*)(p)     = make_float2(wreg[jj].x, wreg[jj].y);
            *(float2*)(p + 2) = make_float2(wreg[jj].z, wreg[jj].w);
        }
        int b = t >> 3, q = t & 7;
        float* p = &Xs[s][b * WSD + 4 * q + 2 * ((b >> 4) & 1)];
        *(float2*)(p)     = make_float2(xreg.x, xreg.y);
        *(float2*)(p + 2) = make_float2(xreg.z, xreg.w);
    };

    unsigned long long acc[4][4];
    #pragma unroll
    for (int i = 0; i < 4; i++)
        #pragma unroll
        for (int j = 0; j < 4; j++) acc[i][j] = 0ull;

    load_tile(0);
    store_tile(0);
    __syncthreads();

    for (int it = 0; it < 16; it++) {
        int cur = it & 1;
        if (it < 15) load_tile((it + 1) * 32);
        const float* W = Wt[cur];
        const float* X = Xs[cur];
        #pragma unroll
        for (int kk = 0; kk < 32; kk += 2) {
            unsigned long long wv[4], xv[4];
            #pragma unroll
            for (int i = 0; i < 4; i++)
                wv[i] = *(const unsigned long long*)(W + (vq * 4 + i) * WSD + kk);
            #pragma unroll
            for (int j = 0; j < 4; j++) {
                int bj = bq * 4 + j;
                xv[j] = *(const unsigned long long*)(X + bj * WSD + kk + 2 * ((bj >> 4) & 1));
            }
            #pragma unroll
            for (int i = 0; i < 4; i++)
                #pragma unroll
                for (int j = 0; j < 4; j++)
                    acc[i][j] = ffma2(wv[i], xv[j], acc[i][j]);
        }
        if (it < 15) store_tile(cur ^ 1);
        __syncthreads();
    }

    float lg[4][4];
    float lmax[4] = { -1e30f, -1e30f, -1e30f, -1e30f };
    #pragma unroll
    for (int i = 0; i < 4; i++) {
        int vv = v0 + vq * 4 + i;
        if (vv < VV) {
            float bias = bo[vv];
            #pragma unroll
            for (int j = 0; j < 4; j++) {
                float lo = __uint_as_float((unsigned)(acc[i][j] & 0xffffffffull));
                float hi = __uint_as_float((unsigned)(acc[i][j] >> 32));
                float l = (lo + hi) + bias;
                lg[i][j] = l;
                lmax[j] = fmaxf(lmax[j], l);
                out[(size_t)(bq * 4 + j) * VV + vv] = l;
            }
        } else {
            #pragma unroll
            for (int j = 0; j < 4; j++) lg[i][j] = -1e30f;
        }
    }

    #pragma unroll
    for (int j = 0; j < 4; j++) red[vq * 32 + bq * 4 + j] = lmax[j];
    __syncthreads();
    for (int off = 16; off > 0; off >>= 1) {
        if (vq < off) {
            #pragma unroll
            for (int j = 0; j < 4; j++) {
                int b = bq * 4 + j;
                red[vq * 32 + b] = fmaxf(red[vq * 32 + b], red[(vq + off) * 32 + b]);
            }
        }
        __syncthreads();
    }
    float mb[4];
    #pragma unroll
    for (int j = 0; j < 4; j++) mb[j] = red[bq * 4 + j];
    __syncthreads();

    float lsum[4] = { 0.f, 0.f, 0.f, 0.f };
    #pragma unroll
    for (int i = 0; i < 4; i++)
        #pragma unroll
        for (int j = 0; j < 4; j++)
            if (lg[i][j] > -1e29f) lsum[j] += expf(lg[i][j] - mb[j]);
    #pragma unroll
    for (int j = 0; j < 4; j++) red[vq * 32 + bq * 4 + j] = lsum[j];
    __syncthreads();
    for (int off = 16; off > 0; off >>= 1) {
        if (vq < off) {
            #pragma unroll
            for (int j = 0; j < 4; j++) {
                int b = bq * 4 + j;
                red[vq * 32 + b] += red[(vq + off) * 32 + b];
            }
        }
        __syncthreads();
    }
    if (vq == 0) {
        #pragma unroll
        for (int j = 0; j < 4; j++) {
            int b = bq * 4 + j;
            g_lsem[blockIdx.x * 32 + b] = mb[j];
            g_lses[blockIdx.x * 32 + b] = red[b];
        }
    }
}

// ---------------- K7: merge per-block LSE partials ----------------
__global__ void k_lse() {
    __shared__ float mred[512], sred[512];
    int b = blockIdx.x, t = threadIdx.x;
    float m = -1e30f, S = 0.f;
    if (t < NBLK) {
        m = g_lsem[t * 32 + b];
        S = g_lses[t * 32 + b];
    }
    mred[t] = m; sred[t] = S;
    __syncthreads();
    for (int off = 256; off > 0; off >>= 1) {
        if (t < off) {
            float m1 = mred[t], m2 = mred[t + off];
            float s1 = sred[t], s2 = sred[t + off];
            float mm = fmaxf(m1, m2);
            mred[t] = mm;
            sred[t] = s1 * expf(m1 - mm) + s2 * expf(m2 - mm);
        }
        __syncthreads();
    }
    if (t == 0) g_lse[b] = mred[0] + logf(sred[0]);
}

// ---------------- K8: log_probs = logits - lse (4-way MLP) ----------------
__global__ void k_sub(float* __restrict__ out) {
    int b = blockIdx.y;
    int v = blockIdx.x * 1024 + threadIdx.x;
    float l = g_lse[b];
    float* p = out + (size_t)b * VV;
    #pragma unroll
    for (int j = 0; j < 4; j++) {
        int vv = v + j * 256;
        if (vv < VV) p[vv] -= l;
    }
}

extern "C" void kernel_launch(void* const* d_in, const int* in_sizes, int n_in,
                              void* d_out, int out_size) {
    const int*   tokens    = (const int*)d_in[0];
    const float* hidden    = (const float*)d_in[1];
    const float* cell      = (const float*)d_in[2];
    const float* enc       = (const float*)d_in[3];
    const float* emb_table = (const float*)d_in[4];
    const float* W_attn    = (const float*)d_in[5];
    // d_in[6] = b_attn unused (softmax shift-invariance)
    const float* vvec      = (const float*)d_in[7];
    const float* W_ih      = (const float*)d_in[8];
    const float* b_ih      = (const float*)d_in[9];
    const float* W_hh      = (const float*)d_in[10];
    const float* b_hh      = (const float*)d_in[11];
    const float* W_out     = (const float*)d_in[12];
    const float* b_out     = (const float*)d_in[13];
    float* out = (float*)d_out;

    k_init<<<36, 256>>>(tokens, emb_table, hidden, W_attn, vvec);       // 1
    {
        dim3 g(NCH, BB);
        kA<<<g, 256>>>(enc);                                             // 2
    }
    kB<<<BB, 256>>>(out);                                                // 3
    {
        dim3 g(1024 / GT, NKS);
        k_gates<<<g, 256>>>(W_ih, b_ih, W_hh, b_hh);                     // 4
    }
    k_lstm<<<BB, 256>>>(cell, out);                                      // 5
    k_logits<<<NBLK, 256>>>(W_out, b_out, out);                          // 6
    k_lse<<<BB, 512>>>();                                                // 7
    {
        dim3 g((VV + 1023) / 1024, BB);
        k_sub<<<g, 256>>>(out);                                          // 8
    }
}

// round 12
// speedup vs baseline: 2.3216x; 1.0392x over previous
#include <cuda_runtime.h>
#include <math.h>

#define BB 32
#define HH 256
#define LL 2048
#define VV 50257
#define K2H 512
#define NBLK 393          // ceil(VV/128)
#define NKS 8             // k-splits for gates
#define NCH 64            // attention l-chunks (32 rows each)

// d_out layout: log_probs[B*V], h_new[B*H], c_new[B*H], attn_weights[B*L]
#define OUT_H  (BB * VV)
#define OUT_C  (OUT_H + BB * HH)
#define OUT_AW (OUT_C + BB * HH)

// ---------------- scratch ----------------
__device__ __align__(16) float g_wpart[4 * 256];        // partial We^T v
__device__ __align__(16) float g_scores[BB * LL];
__device__ __align__(16) float g_ms[BB * NCH];          // per-chunk max
__device__ __align__(16) float g_Ss[BB * NCH];          // per-chunk expsum
__device__ __align__(16) float g_part[BB * NCH * HH];   // per-chunk weighted partials
__device__ __align__(16) float g_xT[768 * 32];          // [k][b] LSTM input transposed
__device__ __align__(16) float g_gpart[NKS * 1024 * 32];// gate partials [ks][g][b]
__device__ __align__(16) float g_x2[BB * K2H];          // concat(h_new, attnap) per b
__device__ __align__(16) float g_lsem[NBLK * 32];       // per-vblock max per b
__device__ __align__(16) float g_lses[NBLK * 32];       // per-vblock expsum per b
__device__ float g_lse[BB];

static __device__ __forceinline__ unsigned long long ffma2(
    unsigned long long a, unsigned long long b, unsigned long long c) {
    unsigned long long d;
    asm("fma.rn.f32x2 %0, %1, %2, %3;" : "=l"(d) : "l"(a), "l"(b), "l"(c));
    return d;
}

static __device__ __forceinline__ float sigf(float x) { return 1.0f / (1.0f + expf(-x)); }

// ---------------- K1: w partials only (4 blocks) ----------------
__global__ void k_init(const float* __restrict__ W_attn, const float* __restrict__ vvec) {
    int t = threadIdx.x;
    int kb = blockIdx.x * 64;
    float a0 = 0, a1 = 0, a2 = 0, a3 = 0;
    #pragma unroll 4
    for (int i = 0; i < 64; i += 4) {
        a0 = fmaf(vvec[kb + i + 0], W_attn[(kb + i + 0) * 512 + 256 + t], a0);
        a1 = fmaf(vvec[kb + i + 1], W_attn[(kb + i + 1) * 512 + 256 + t], a1);
        a2 = fmaf(vvec[kb + i + 2], W_attn[(kb + i + 2) * 512 + 256 + t], a2);
        a3 = fmaf(vvec[kb + i + 3], W_attn[(kb + i + 3) * 512 + 256 + t], a3);
    }
    g_wpart[blockIdx.x * 256 + t] = (a0 + a1) + (a2 + a3);
}

// ---------------- K2: fused attention pass 1 — per (chunk c, batch b), 32 rows/chunk ------
__global__ void kA(const float* __restrict__ enc) {
    __shared__ float es[32 * 256];      // 32 KB
    __shared__ float w_s[256];
    __shared__ float score_s[32];
    __shared__ float esc_s[32];
    __shared__ float mred_s[1];
    int c = blockIdx.x, b = blockIdx.y;
    int t = threadIdx.x;
    int lane = t & 31, wid = t >> 5;

    w_s[t] = g_wpart[t] + g_wpart[256 + t] + g_wpart[512 + t] + g_wpart[768 + t];

    const float4* e4 = (const float4*)(enc + ((size_t)b * LL + c * 32) * HH);
    float4* s4 = (float4*)es;
    #pragma unroll
    for (int i = 0; i < 8; i++) s4[t + 256 * i] = e4[t + 256 * i];
    __syncthreads();

    const float4* w4 = (const float4*)w_s;
    float4 wa = w4[lane], wb = w4[32 + lane];
    #pragma unroll
    for (int r = wid; r < 32; r += 8) {
        const float4* row = (const float4*)(es + r * 256);
        float4 a = row[lane], cc = row[32 + lane];
        float s = a.x * wa.x + a.y * wa.y + a.z * wa.z + a.w * wa.w
                + cc.x * wb.x + cc.y * wb.y + cc.z * wb.z + cc.w * wb.w;
        #pragma unroll
        for (int off = 16; off > 0; off >>= 1)
            s += __shfl_xor_sync(0xffffffffu, s, off);
        if (lane == 0) {
            score_s[r] = s;
            g_scores[b * LL + c * 32 + r] = s;
        }
    }
    __syncthreads();

    if (t < 32) {
        float m = score_s[t];
        #pragma unroll
        for (int off = 16; off > 0; off >>= 1)
            m = fmaxf(m, __shfl_xor_sync(0xffffffffu, m, off));
        if (lane == 0) mred_s[0] = m;
        __syncwarp();
        float m_c = mred_s[0];
        float e = expf(score_s[t] - m_c);
        esc_s[t] = e;
        float sum = e;
        #pragma unroll
        for (int off = 16; off > 0; off >>= 1)
            sum += __shfl_xor_sync(0xffffffffu, sum, off);
        if (lane == 0) { g_ms[b * NCH + c] = m_c; g_Ss[b * NCH + c] = sum; }
    }
    __syncthreads();

    float a0 = 0, a1 = 0, a2 = 0, a3 = 0;
    #pragma unroll
    for (int l = 0; l < 32; l += 4) {
        a0 = fmaf(esc_s[l + 0], es[(l + 0) * 256 + t], a0);
        a1 = fmaf(esc_s[l + 1], es[(l + 1) * 256 + t], a1);
        a2 = fmaf(esc_s[l + 2], es[(l + 2) * 256 + t], a2);
        a3 = fmaf(esc_s[l + 3], es[(l + 3) * 256 + t], a3);
    }
    g_part[((size_t)b * NCH + c) * 256 + t] = (a0 + a1) + (a2 + a3);
}

// ---------------- K3: attention combine + emb/hidden transpose ----------------
__global__ void kB(float* __restrict__ out,
                   const int* __restrict__ tokens,
                   const float* __restrict__ emb_table,
                   const float* __restrict__ hidden) {
    __shared__ float mc_s[NCH], Ss_s[NCH], mred[NCH], scale_s[NCH];
    __shared__ float stat_s[2];
    int b = blockIdx.x, t = threadIdx.x;

    // absorbed from k_init: emb + hidden -> g_xT (independent of attention math)
    int tok = tokens[b];
    g_xT[t * 32 + b] = emb_table[(long long)tok * HH + t];
    g_xT[(512 + t) * 32 + b] = hidden[b * HH + t];

    if (t < NCH) {
        mc_s[t] = g_ms[b * NCH + t];
        Ss_s[t] = g_Ss[b * NCH + t];
        mred[t] = mc_s[t];
    }
    __syncthreads();
    for (int off = NCH / 2; off > 0; off >>= 1) {
        if (t < off) mred[t] = fmaxf(mred[t], mred[t + off]);
        __syncthreads();
    }
    float m = mred[0];
    if (t < NCH) {
        float e = expf(mc_s[t] - m);
        scale_s[t] = e;
        mred[t] = Ss_s[t] * e;
    }
    __syncthreads();
    for (int off = NCH / 2; off > 0; off >>= 1) {
        if (t < off) mred[t] += mred[t + off];
        __syncthreads();
    }
    float invZ = 1.0f / mred[0];
    if (t == 0) { stat_s[0] = m; stat_s[1] = invZ; }
    if (t < NCH) scale_s[t] *= invZ;
    __syncthreads();

    float s0 = 0, s1 = 0, s2 = 0, s3 = 0;
    #pragma unroll
    for (int c = 0; c < NCH; c += 4) {
        s0 = fmaf(g_part[((size_t)b * NCH + c + 0) * 256 + t], scale_s[c + 0], s0);
        s1 = fmaf(g_part[((size_t)b * NCH + c + 1) * 256 + t], scale_s[c + 1], s1);
        s2 = fmaf(g_part[((size_t)b * NCH + c + 2) * 256 + t], scale_s[c + 2], s2);
        s3 = fmaf(g_part[((size_t)b * NCH + c + 3) * 256 + t], scale_s[c + 3], s3);
    }
    float s = (s0 + s1) + (s2 + s3);
    g_x2[b * K2H + 256 + t] = s;
    g_xT[(256 + t) * 32 + b] = s;

    float mm = stat_s[0], iz = stat_s[1];
    const float4* sc4 = (const float4*)(g_scores + b * LL + t * 8);
    float4* o4 = (float4*)(out + OUT_AW + b * LL + t * 8);
    float4 v0 = sc4[0], v1 = sc4[1];
    float4 r0, r1;
    r0.x = expf(v0.x - mm) * iz; r0.y = expf(v0.y - mm) * iz;
    r0.z = expf(v0.z - mm) * iz; r0.w = expf(v0.w - mm) * iz;
    r1.x = expf(v1.x - mm) * iz; r1.y = expf(v1.y - mm) * iz;
    r1.z = expf(v1.z - mm) * iz; r1.w = expf(v1.w - mm) * iz;
    o4[0] = r0; o4[1] = r1;
}

// ---------------- K4: LSTM gates GEMM — smem-tiled, 256 blocks ----------------
#define GT 32
#define KT 96
__global__ void k_gates(const float* __restrict__ W_ih, const float* __restrict__ b_ih,
                        const float* __restrict__ W_hh, const float* __restrict__ b_hh) {
    __shared__ float Ws[GT * KT];   // 12 KB  [g][k]
    __shared__ float xs[KT * 32];   // 12 KB  [k][b]
    int t = threadIdx.x;
    int g0 = blockIdx.x * GT;
    int ks = blockIdx.y;
    int klo = ks * KT;

    #pragma unroll
    for (int i = 0; i < GT * KT / 256; i++) {
        int idx = t + i * 256;
        int g = idx / KT, kk = idx - g * KT;
        int kg = klo + kk;
        float v = (kg < 512) ? W_ih[(size_t)(g0 + g) * 512 + kg]
                             : W_hh[(size_t)(g0 + g) * 256 + (kg - 512)];
        Ws[g * KT + kk] = v;
    }
    #pragma unroll
    for (int i = 0; i < KT * 32 / 256; i++) {
        int idx = t + i * 256;
        xs[idx] = g_xT[klo * 32 + idx];
    }
    __syncthreads();

    int lane = t & 31, w = t >> 5;
    int gl = w * 4;
    float acc[4] = {0, 0, 0, 0};
    #pragma unroll 4
    for (int kk = 0; kk < KT; kk += 2) {
        float x0 = xs[kk * 32 + lane];
        float x1 = xs[(kk + 1) * 32 + lane];
        #pragma unroll
        for (int g = 0; g < 4; g++) {
            float2 wp = *(const float2*)&Ws[(gl + g) * KT + kk];
            acc[g] = fmaf(wp.x, x0, fmaf(wp.y, x1, acc[g]));
        }
    }
    float* gp = g_gpart + ks * 32768;
    #pragma unroll
    for (int g = 0; g < 4; g++) {
        float a = acc[g];
        int gr = g0 + gl + g;
        if (ks == 0) a += b_ih[gr] + b_hh[gr];
        gp[gr * 32 + lane] = a;
    }
}

// ---------------- K5: LSTM pointwise (sums 8 k-split partials) ----------------
__global__ void k_lstm(const float* __restrict__ cell, float* __restrict__ out) {
    int b = blockIdx.x, h = threadIdx.x;
    float ig = 0, fg = 0, gg = 0, og = 0;
    #pragma unroll
    for (int ks = 0; ks < NKS; ks++) {
        const float* gp = g_gpart + ks * 32768;
        ig += gp[(0 * HH + h) * 32 + b];
        fg += gp[(1 * HH + h) * 32 + b];
        gg += gp[(2 * HH + h) * 32 + b];
        og += gp[(3 * HH + h) * 32 + b];
    }
    float c_new = sigf(fg) * cell[b * HH + h] + sigf(ig) * tanhf(gg);
    float h_new = sigf(og) * tanhf(c_new);
    out[OUT_H + b * HH + h] = h_new;
    out[OUT_C + b * HH + h] = c_new;
    g_x2[b * K2H + h] = h_new;
}

// ---------------- K6: logits GEMM — f32x2 packed over even/odd k, 3 blocks/SM ----------
#define WSD 34
__global__ void __launch_bounds__(256, 3) k_logits(const float* __restrict__ Wo,
                                                   const float* __restrict__ bo,
                                                   float* __restrict__ out) {
    __shared__ float Wt[2][128 * WSD];
    __shared__ float Xs[2][32 * WSD + 8];
    __shared__ float red[32 * 32];        // [vq][b] reduction scratch

    int t = threadIdx.x;
    int v0 = blockIdx.x * 128;
    int vq = t >> 3, bq = t & 7;

    float4 wreg[4];
    float4 xreg;

    auto load_tile = [&](int kt) {
        #pragma unroll
        for (int jj = 0; jj < 4; jj++) {
            int idx = jj * 256 + t;
            int row = idx >> 3, q = idx & 7;
            int vr = v0 + row;
            wreg[jj] = (vr < VV) ? *(const float4*)(Wo + (size_t)vr * 512 + kt + 4 * q)
                                 : make_float4(0.f, 0.f, 0.f, 0.f);
        }
        xreg = *(const float4*)(g_x2 + (t >> 3) * K2H + kt + 4 * (t & 7));
    };
    auto store_tile = [&](int s) {
        #pragma unroll
        for (int jj = 0; jj < 4; jj++) {
            int idx = jj * 256 + t;
            int row = idx >> 3, q = idx & 7;
            float* p = &Wt[s][row * WSD + 4 * q];
            *(float2*)(p)     = make_float2(wreg[jj].x, wreg[jj].y);
            *(float2*)(p + 2) = make_float2(wreg[jj].z, wreg[jj].w);
        }
        int b = t >> 3, q = t & 7;
        float* p = &Xs[s][b * WSD + 4 * q + 2 * ((b >> 4) & 1)];
        *(float2*)(p)     = make_float2(xreg.x, xreg.y);
        *(float2*)(p + 2) = make_float2(xreg.z, xreg.w);
    };

    unsigned long long acc[4][4];
    #pragma unroll
    for (int i = 0; i < 4; i++)
        #pragma unroll
        for (int j = 0; j < 4; j++) acc[i][j] = 0ull;

    load_tile(0);
    store_tile(0);
    __syncthreads();

    for (int it = 0; it < 16; it++) {
        int cur = it & 1;
        if (it < 15) load_tile((it + 1) * 32);
        const float* W = Wt[cur];
        const float* X = Xs[cur];
        #pragma unroll
        for (int kk = 0; kk < 32; kk += 2) {
            unsigned long long wv[4], xv[4];
            #pragma unroll
            for (int i = 0; i < 4; i++)
                wv[i] = *(const unsigned long long*)(W + (vq * 4 + i) * WSD + kk);
            #pragma unroll
            for (int j = 0; j < 4; j++) {
                int bj = bq * 4 + j;
                xv[j] = *(const unsigned long long*)(X + bj * WSD + kk + 2 * ((bj >> 4) & 1));
            }
            #pragma unroll
            for (int i = 0; i < 4; i++)
                #pragma unroll
                for (int j = 0; j < 4; j++)
                    acc[i][j] = ffma2(wv[i], xv[j], acc[i][j]);
        }
        if (it < 15) store_tile(cur ^ 1);
        __syncthreads();
    }

    float lg[4][4];
    float lmax[4] = { -1e30f, -1e30f, -1e30f, -1e30f };
    #pragma unroll
    for (int i = 0; i < 4; i++) {
        int vv = v0 + vq * 4 + i;
        if (vv < VV) {
            float bias = bo[vv];
            #pragma unroll
            for (int j = 0; j < 4; j++) {
                float lo = __uint_as_float((unsigned)(acc[i][j] & 0xffffffffull));
                float hi = __uint_as_float((unsigned)(acc[i][j] >> 32));
                float l = (lo + hi) + bias;
                lg[i][j] = l;
                lmax[j] = fmaxf(lmax[j], l);
                out[(size_t)(bq * 4 + j) * VV + vv] = l;
            }
        } else {
            #pragma unroll
            for (int j = 0; j < 4; j++) lg[i][j] = -1e30f;
        }
    }

    #pragma unroll
    for (int j = 0; j < 4; j++) red[vq * 32 + bq * 4 + j] = lmax[j];
    __syncthreads();
    for (int off = 16; off > 0; off >>= 1) {
        if (vq < off) {
            #pragma unroll
            for (int j = 0; j < 4; j++) {
                int b = bq * 4 + j;
                red[vq * 32 + b] = fmaxf(red[vq * 32 + b], red[(vq + off) * 32 + b]);
            }
        }
        __syncthreads();
    }
    float mb[4];
    #pragma unroll
    for (int j = 0; j < 4; j++) mb[j] = red[bq * 4 + j];
    __syncthreads();

    float lsum[4] = { 0.f, 0.f, 0.f, 0.f };
    #pragma unroll
    for (int i = 0; i < 4; i++)
        #pragma unroll
        for (int j = 0; j < 4; j++)
            if (lg[i][j] > -1e29f) lsum[j] += expf(lg[i][j] - mb[j]);
    #pragma unroll
    for (int j = 0; j < 4; j++) red[vq * 32 + bq * 4 + j] = lsum[j];
    __syncthreads();
    for (int off = 16; off > 0; off >>= 1) {
        if (vq < off) {
            #pragma unroll
            for (int j = 0; j < 4; j++) {
                int b = bq * 4 + j;
                red[vq * 32 + b] += red[(vq + off) * 32 + b];
            }
        }
        __syncthreads();
    }
    if (vq == 0) {
        #pragma unroll
        for (int j = 0; j < 4; j++) {
            int b = bq * 4 + j;
            g_lsem[blockIdx.x * 32 + b] = mb[j];
            g_lses[blockIdx.x * 32 + b] = red[b];
        }
    }
}

// ---------------- K7: merge per-block LSE partials ----------------
__global__ void k_lse() {
    __shared__ float mred[512], sred[512];
    int b = blockIdx.x, t = threadIdx.x;
    float m = -1e30f, S = 0.f;
    if (t < NBLK) {
        m = g_lsem[t * 32 + b];
        S = g_lses[t * 32 + b];
    }
    mred[t] = m; sred[t] = S;
    __syncthreads();
    for (int off = 256; off > 0; off >>= 1) {
        if (t < off) {
            float m1 = mred[t], m2 = mred[t + off];
            float s1 = sred[t], s2 = sred[t + off];
            float mm = fmaxf(m1, m2);
            mred[t] = mm;
            sred[t] = s1 * expf(m1 - mm) + s2 * expf(m2 - mm);
        }
        __syncthreads();
    }
    if (t == 0) g_lse[b] = mred[0] + logf(sred[0]);
}

// ---------------- K8: log_probs -= lse, flat float4 (B*V divisible by 4) ----------------
__global__ void k_sub(float* __restrict__ out) {
    const int NF4 = (BB * VV) / 4;        // 402056
    int base = blockIdx.x * 1024 + threadIdx.x;
    float4* o4 = (float4*)out;
    #pragma unroll
    for (int j = 0; j < 4; j++) {
        int f = base + j * 256;
        if (f < NF4) {
            int e0 = f * 4;
            int b0 = e0 / VV;
            int bnd = (b0 + 1) * VV;
            float l0 = g_lse[b0];
            float l1 = (b0 < BB - 1) ? g_lse[b0 + 1] : 0.f;
            float4 v = o4[f];
            v.x -= (e0 + 0 >= bnd) ? l1 : l0;
            v.y -= (e0 + 1 >= bnd) ? l1 : l0;
            v.z -= (e0 + 2 >= bnd) ? l1 : l0;
            v.w -= (e0 + 3 >= bnd) ? l1 : l0;
            o4[f] = v;
        }
    }
}

extern "C" void kernel_launch(void* const* d_in, const int* in_sizes, int n_in,
                              void* d_out, int out_size) {
    const int*   tokens    = (const int*)d_in[0];
    const float* hidden    = (const float*)d_in[1];
    const float* cell      = (const float*)d_in[2];
    const float* enc       = (const float*)d_in[3];
    const float* emb_table = (const float*)d_in[4];
    const float* W_attn    = (const float*)d_in[5];
    // d_in[6] = b_attn unused (softmax shift-invariance)
    const float* vvec      = (const float*)d_in[7];
    const float* W_ih      = (const float*)d_in[8];
    const float* b_ih      = (const float*)d_in[9];
    const float* W_hh      = (const float*)d_in[10];
    const float* b_hh      = (const float*)d_in[11];
    const float* W_out     = (const float*)d_in[12];
    const float* b_out     = (const float*)d_in[13];
    float* out = (float*)d_out;

    k_init<<<4, 256>>>(W_attn, vvec);                                    // 1
    {
        dim3 g(NCH, BB);
        kA<<<g, 256>>>(enc);                                             // 2
    }
    kB<<<BB, 256>>>(out, tokens, emb_table, hidden);                     // 3
    {
        dim3 g(1024 / GT, NKS);
        k_gates<<<g, 256>>>(W_ih, b_ih, W_hh, b_hh);                     // 4
    }
    k_lstm<<<BB, 256>>>(cell, out);                                      // 5
    k_logits<<<NBLK, 256>>>(W_out, b_out, out);                          // 6
    k_lse<<<BB, 512>>>();                                                // 7
    {
        const int NF4 = (BB * VV) / 4;
        k_sub<<<(NF4 + 1023) / 1024, 256>>>(out);                        // 8
    }
}